// round 6
// baseline (speedup 1.0000x reference)
#include <cuda_runtime.h>
#include <cuda_fp16.h>
#include <math.h>

#define NB 16
#define NH 16
#define NHD 64
#define ND 1024
#define NL 513
#define NP 1024

// Scratch (allocation-free rule: __device__ globals)
__device__ float g_QC[NB*NH*NL*NHD];   // q + content_bias, [b,h,l,hd]
__device__ float g_QP[NB*NH*NL*NHD];   // q + position_bias
__device__ float g_Kt[NB*NH*NL*NHD];   // k, [b,h,l,hd]
__device__ float g_Vt[NB*NH*NL*NHD];   // v, [b,h,l,hd]
__device__ float g_PT[NB*NH*NP*NHD];   // pos projected, transposed: [b,h,p,hd]
__device__ float g_CTX[NB*NL*ND];      // attention output, [b,l,h*64+hd]

__device__ __forceinline__ unsigned cvt_tf32(float f) {
    unsigned u;
    asm("cvt.rna.tf32.f32 %0, %1;" : "=r"(u) : "f"(f));
    return u;
}

__device__ __forceinline__ void mma_tf32(float* d, const uint4& a, const uint2& b) {
    asm volatile(
        "mma.sync.aligned.m16n8k8.row.col.f32.tf32.tf32.f32 "
        "{%0,%1,%2,%3}, {%4,%5,%6,%7}, {%8,%9}, {%0,%1,%2,%3};"
        : "+f"(d[0]), "+f"(d[1]), "+f"(d[2]), "+f"(d[3])
        : "r"(a.x), "r"(a.y), "r"(a.z), "r"(a.w), "r"(b.x), "r"(b.y));
}

__device__ __forceinline__ void mma_f16(float* d, const uint4& a, const uint2& b) {
    asm volatile(
        "mma.sync.aligned.m16n8k16.row.col.f32.f16.f16.f32 "
        "{%0,%1,%2,%3}, {%4,%5,%6,%7}, {%8,%9}, {%0,%1,%2,%3};"
        : "+f"(d[0]), "+f"(d[1]), "+f"(d[2]), "+f"(d[3])
        : "r"(a.x), "r"(a.y), "r"(a.z), "r"(a.w), "r"(b.x), "r"(b.y));
}

__device__ __forceinline__ unsigned pkh2(float x, float y) {
    __half2 h = __floats2half2_rn(x, y);
    return *(unsigned*)&h;
}

// ---------------------------------------------------------------------------
// tf32 tensor-core GEMM, double-buffered (BK=16): C = A @ Bw^T (+epilogue)
// 256 thr / 8 warps (2M x 4N of 64x32 tiles). One sync per K-chunk; LDG of
// chunk k+1 issued before the MMAs of chunk k.
// ---------------------------------------------------------------------------
template<int EPI>
__global__ void __launch_bounds__(256, 2)
gemm_tf32(const float* __restrict__ A, const float* __restrict__ Bw,
          int M, int N,
          const float* __restrict__ bias,
          const float* __restrict__ cbias, const float* __restrict__ pbias,
          float* __restrict__ out)
{
    const int K = 1024;
    __shared__ unsigned sA[2 * 2120];
    __shared__ unsigned sB[2 * 2052];

    int t    = threadIdx.x;
    int lane = t & 31, w = t >> 5;
    int warpM = w & 1, warpN = w >> 1;
    int m0 = blockIdx.y * 128, n0 = blockIdx.x * 128;

    int lrow = t >> 2;        // 0..63
    int lkq  = t & 3;         // float4 slot along 16-wide k
    int ksL  = lkq >> 1;
    int frp  = lkq & 1;

    // precomputed staging addresses (same for both rows handled via +u*64)
    unsigned baA[2], baB[2];
#pragma unroll
    for (int u = 0; u < 2; u++) {
        int ml = lrow + u * 64;
        int mt = ml >> 4, mp = ml & 15;
        baA[u] = ksL * 1060 + mt * 132 + (mp & 7) * 16 + frp * 2 + (mp >> 3);
        baB[u] = ksL * 1026 + (ml >> 3) * 64 + (ml & 7) * 8 + frp;
    }

    float acc[4][4][4];
#pragma unroll
    for (int i = 0; i < 4; i++)
#pragma unroll
        for (int j = 0; j < 4; j++)
#pragma unroll
            for (int r = 0; r < 4; r++) acc[i][j][r] = 0.f;

    float4 ra[2], rb[2];
    const float4 z4 = make_float4(0.f, 0.f, 0.f, 0.f);

#define GLOAD(KT) {                                                          \
        _Pragma("unroll")                                                    \
        for (int u = 0; u < 2; u++) {                                        \
            int gm = m0 + lrow + u * 64;                                     \
            ra[u] = (gm < M) ? *(const float4*)(A + (size_t)gm * K + (KT) + lkq * 4) : z4; \
            rb[u] = *(const float4*)(Bw + (size_t)(n0 + lrow + u * 64) * K + (KT) + lkq * 4); \
        } }

#define SSTORE(BI) {                                                         \
        _Pragma("unroll")                                                    \
        for (int u = 0; u < 2; u++) {                                        \
            unsigned ba = (BI) * 2120 + baA[u];                              \
            sA[ba + 0]  = cvt_tf32(ra[u].x); sA[ba + 4]  = cvt_tf32(ra[u].y);\
            sA[ba + 8]  = cvt_tf32(ra[u].z); sA[ba + 12] = cvt_tf32(ra[u].w);\
            unsigned bb = (BI) * 2052 + baB[u];                              \
            sB[bb + 0] = cvt_tf32(rb[u].x); sB[bb + 2] = cvt_tf32(rb[u].y);  \
            sB[bb + 4] = cvt_tf32(rb[u].z); sB[bb + 6] = cvt_tf32(rb[u].w);  \
        } }

    GLOAD(0); SSTORE(0);
    __syncthreads();

#pragma unroll 2
    for (int c16 = 0; c16 < 64; c16++) {
        int cur = c16 & 1;
        if (c16 + 1 < 64) GLOAD((c16 + 1) * 16);
#pragma unroll
        for (int ks = 0; ks < 2; ks++) {
            uint4 av[4];
            uint2 bv[4];
#pragma unroll
            for (int i = 0; i < 4; i++)
                av[i] = *(const uint4*)&sA[cur * 2120 + ks * 1060 + (warpM * 4 + i) * 132 + lane * 4];
#pragma unroll
            for (int j = 0; j < 4; j++)
                bv[j] = *(const uint2*)&sB[cur * 2052 + ks * 1026 + (warpN * 4 + j) * 64 + lane * 2];
#pragma unroll
            for (int i = 0; i < 4; i++)
#pragma unroll
                for (int j = 0; j < 4; j++)
                    mma_tf32(acc[i][j], av[i], bv[j]);
        }
        if (c16 + 1 < 64) SSTORE(1 - cur);
        __syncthreads();
    }
#undef GLOAD
#undef SSTORE

    int mb = m0 + warpM * 64 + (lane >> 2);
    int nb = n0 + warpN * 32 + (lane & 3) * 2;
#pragma unroll
    for (int i = 0; i < 4; i++) {
#pragma unroll
        for (int rr = 0; rr < 2; rr++) {
            int m = mb + i * 16 + rr * 8;
            if (m >= M) continue;
            if (EPI == 0) {
                int b_ = m / NL, l = m - b_ * NL;
#pragma unroll
                for (int j = 0; j < 4; j++) {
                    int n = nb + j * 8;            // even; pair (n, n+1) same part/head
                    float v0 = acc[i][j][rr * 2 + 0] + bias[n];
                    float v1 = acc[i][j][rr * 2 + 1] + bias[n + 1];
                    int part = n >> 10, c1 = n & 1023;
                    int hh = c1 >> 6, hd = c1 & 63;
                    size_t o = ((((size_t)b_ * NH + hh) * NL + l) << 6) + hd;
                    if (part == 0) {
                        *(float2*)&g_QC[o] = make_float2(v0 + cbias[c1], v1 + cbias[c1 + 1]);
                        *(float2*)&g_QP[o] = make_float2(v0 + pbias[c1], v1 + pbias[c1 + 1]);
                    } else if (part == 1) {
                        *(float2*)&g_Kt[o] = make_float2(v0, v1);
                    } else {
                        *(float2*)&g_Vt[o] = make_float2(v0, v1);
                    }
                }
            } else if (EPI == 1) {
                float bm = bias[m];
#pragma unroll
                for (int j = 0; j < 4; j++) {
                    int n = nb + j * 8;
                    float v0 = acc[i][j][rr * 2 + 0] + bm;
                    float v1 = acc[i][j][rr * 2 + 1] + bm;
                    int bh = n >> 6, hd = n & 63;
                    *(float2*)&g_PT[((((size_t)bh) << 10) + m) * 64 + hd] = make_float2(v0, v1);
                }
            } else {
#pragma unroll
                for (int j = 0; j < 4; j++) {
                    int n = nb + j * 8;
                    float2 st;
                    st.x = acc[i][j][rr * 2 + 0] + bias[n];
                    st.y = acc[i][j][rr * 2 + 1] + bias[n + 1];
                    *(float2*)(out + (size_t)m * ND + n) = st;
                }
            }
        }
    }
}

// ---------------------------------------------------------------------------
// Tensor-core fused attention. CTA = (i-tile of 64 q, one b,h), 256 thr/8 warps.
// warp w: row group rg=w&3 (16 rows), column half ch=w>>2.
//  score:  S = QC@K^T (tf32) + diag-gather( G = QP@Pband^T (f16, band-pruned) )
//  softmax (half2-vectorized) on fp16 S in smem, AV = exp(S)@V (tf32).
// smem 108,160B -> 2 CTAs/SM.
// ---------------------------------------------------------------------------
__global__ void __launch_bounds__(256, 2)
attn_mma(const unsigned char* __restrict__ mask, float* __restrict__ ctx)
{
    extern __shared__ char smraw[];
    __half*   sS  = (__half*)smraw;                   // [64][520] + 64 pad halves
    unsigned* sKG = (unsigned*)(smraw + 66688);       // K/V tf32 frags | G f16 (16,640B)
    unsigned* sP  = (unsigned*)(smraw + 83328);       // P band f16 frags (16,384B)
    unsigned* sQP = (unsigned*)(smraw + 99712);       // QP f16 A-frags (8,192B)
    float*    sSum= (float*)(smraw + 107904);         // [64]
    __half*   sG  = (__half*)sKG;                     // G view: [64][130] halves

    int t = threadIdx.x, lam = t & 31, w = t >> 5;
    int rg = w & 3, ch = w >> 2;
    int it = blockIdx.x, h = blockIdx.y, b = blockIdx.z;
    int i0 = it * 64;
    size_t bh = (size_t)b * NH + h;
    const float* QCg = g_QC + bh * NL * NHD;
    const float* QPg = g_QP + bh * NL * NHD;
    const float* Kg  = g_Kt + bh * NL * NHD;
    const float* Vg  = g_Vt + bh * NL * NHD;
    const float* Pg  = g_PT + bh * NP * NHD;

    // zero sS (incl. pads)
    for (int idx = t; idx < 16672; idx += 256) ((unsigned*)sS)[idx] = 0u;

    int gr0 = rg * 16 + (lam >> 2);
    int r0g = i0 + gr0, r1g = r0g + 8;
    int gt0 = 6 - 2 * rg;      // first G n8-tile needed by this row group

    // QC A-frags (tf32) in registers: 8 ksteps
    uint4 qcf[8];
#pragma unroll
    for (int ks = 0; ks < 8; ks++) {
        int c0 = ks * 8 + (lam & 3);
        float a0 = (r0g < NL) ? QCg[r0g * 64 + c0]     : 0.f;
        float a1 = (r1g < NL) ? QCg[r1g * 64 + c0]     : 0.f;
        float a2 = (r0g < NL) ? QCg[r0g * 64 + c0 + 4] : 0.f;
        float a3 = (r1g < NL) ? QCg[r1g * 64 + c0 + 4] : 0.f;
        qcf[ks] = make_uint4(cvt_tf32(a0), cvt_tf32(a1), cvt_tf32(a2), cvt_tf32(a3));
    }

    // stage QP f16 A-frags
    {
        int rgs = w & 3;
        int rs0 = i0 + rgs * 16 + (lam >> 2), rs1 = rs0 + 8;
#pragma unroll
        for (int si = 0; si < 2; si++) {
            int s = (w >> 2) * 2 + si;
            int k2 = s * 16 + 2 * (lam & 3);
            float q00 = 0, q01 = 0, q10 = 0, q11 = 0, q02 = 0, q03 = 0, q12 = 0, q13 = 0;
            if (rs0 < NL) {
                q00 = QPg[rs0 * 64 + k2];     q01 = QPg[rs0 * 64 + k2 + 1];
                q02 = QPg[rs0 * 64 + k2 + 8]; q03 = QPg[rs0 * 64 + k2 + 9];
            }
            if (rs1 < NL) {
                q10 = QPg[rs1 * 64 + k2];     q11 = QPg[rs1 * 64 + k2 + 1];
                q12 = QPg[rs1 * 64 + k2 + 8]; q13 = QPg[rs1 * 64 + k2 + 9];
            }
            uint4 v = make_uint4(pkh2(q00, q01), pkh2(q10, q11),
                                 pkh2(q02, q03), pkh2(q12, q13));
            *(uint4*)&sQP[(rgs * 4 + s) * 128 + lam * 4] = v;
        }
    }

    // ===================== score phase =====================
    for (int jt = 0; jt < 9; jt++) {
        int j0 = jt * 64;
        __syncthreads();
        // stage K_j as tf32 B-frags (k-dim = hd, n-dim = key)
#pragma unroll
        for (int u = 0; u < 4; u++) {
            int key = (t >> 4) + u * 16;
            int hd4 = (t & 15) * 4;
            int gk = j0 + key;
            float4 kv = make_float4(0.f, 0.f, 0.f, 0.f);
            if (gk < NL) kv = *(const float4*)(Kg + (size_t)gk * 64 + hd4);
            int ks = hd4 >> 3, khigh = (hd4 & 7) >> 2;
            unsigned base = ks * 520 + (key >> 3) * 64 + (key & 7) * 8 + khigh;
            sKG[base + 0] = cvt_tf32(kv.x);
            sKG[base + 2] = cvt_tf32(kv.y);
            sKG[base + 4] = cvt_tf32(kv.z);
            sKG[base + 6] = cvt_tf32(kv.w);
        }
        // stage P band (128 rows x 64 hd) as f16 B-frags, float4 sources
        int pbase = j0 - i0 + 449;
#pragma unroll
        for (int u = 0; u < 8; u++) {
            int idx = u * 256 + t;
            int c = idx >> 4, d4 = (idx & 15) * 4;
            int p = pbase + c;
            unsigned h0 = 0u, h1 = 0u;
            if ((unsigned)p < (unsigned)NP) {
                float4 pv = *(const float4*)(Pg + (size_t)p * 64 + d4);
                h0 = pkh2(pv.x, pv.y);
                h1 = pkh2(pv.z, pv.w);
            }
            int step = d4 >> 4, d16 = d4 & 15;
            unsigned a0 = step * 1024 + (c >> 3) * 64 + ((c & 7) * 4 + ((d16 & 7) >> 1)) * 2 + (d16 >> 3);
            sP[a0]     = h0;
            sP[a0 + 2] = h1;
        }
        __syncthreads();

        // content MMA (tf32): 4 n8-tiles
        float C[4][4];
#pragma unroll
        for (int nt = 0; nt < 4; nt++)
#pragma unroll
            for (int r = 0; r < 4; r++) C[nt][r] = 0.f;
#pragma unroll
        for (int ks = 0; ks < 8; ks++) {
            uint4 av = qcf[ks];
#pragma unroll
            for (int nt = 0; nt < 4; nt++) {
                uint2 bv = *(const uint2*)&sKG[ks * 520 + (ch * 4 + nt) * 64 + lam * 2];
                mma_tf32(C[nt], av, bv);
            }
        }
        // G MMA (f16): only the 10 band tiles this row group needs (5 per ch)
        float G[5][4];
#pragma unroll
        for (int nt = 0; nt < 5; nt++)
#pragma unroll
            for (int r = 0; r < 4; r++) G[nt][r] = 0.f;
#pragma unroll
        for (int s = 0; s < 4; s++) {
            uint4 af = *(const uint4*)&sQP[(rg * 4 + s) * 128 + lam * 4];
#pragma unroll
            for (int nt = 0; nt < 5; nt++) {
                int tg = gt0 + ch * 5 + nt;
                uint2 bv = *(const uint2*)&sP[s * 1024 + tg * 64 + lam * 2];
                mma_f16(G[nt], af, bv);
            }
        }
        __syncthreads();   // content reads of sKG done before G overwrite
#pragma unroll
        for (int nt = 0; nt < 5; nt++) {
            int c0 = (gt0 + ch * 5 + nt) * 8 + 2 * (lam & 3);
            *(__half2*)&sG[gr0 * 130 + c0]       = __floats2half2_rn(G[nt][0], G[nt][1]);
            *(__half2*)&sG[(gr0 + 8) * 130 + c0] = __floats2half2_rn(G[nt][2], G[nt][3]);
        }
        __syncthreads();   // G visible
#pragma unroll
        for (int nt = 0; nt < 4; nt++) {
            int jjb = ch * 32 + nt * 8 + 2 * (lam & 3);
            float s0 = C[nt][0] + __half2float(sG[gr0 * 130 + (jjb - gr0 + 63)]);
            float s1 = C[nt][1] + __half2float(sG[gr0 * 130 + (jjb + 1 - gr0 + 63)]);
            float s2 = C[nt][2] + __half2float(sG[(gr0 + 8) * 130 + (jjb - gr0 - 8 + 63)]);
            float s3 = C[nt][3] + __half2float(sG[(gr0 + 8) * 130 + (jjb + 1 - gr0 - 8 + 63)]);
            if (j0 + jjb < NL) {
                *(__half2*)&sS[gr0 * 520 + j0 + jjb]       = __floats2half2_rn(s0, s1);
                *(__half2*)&sS[(gr0 + 8) * 520 + j0 + jjb] = __floats2half2_rn(s2, s3);
            }
        }
    }
    __syncthreads();

    // ===================== softmax (warp per row, half2) =====================
    for (int li = w * 8; li < w * 8 + 8; li++) {
        int i = i0 + li;
        if (i >= NL) { if (lam == 0) sSum[li] = 1.f; continue; }
        const unsigned char* mrow = mask + ((size_t)b * NL + i) * NL;
        __half2* srow2 = (__half2*)&sS[li * 520];
        float mx = -3.4028235e38f;
        for (int j2 = lam; j2 < 256; j2 += 32) {
            float2 v = __half22float2(srow2[j2]);
            v.x = mrow[2 * j2]     ? -3.4028235e38f : v.x * 0.125f;
            v.y = mrow[2 * j2 + 1] ? -3.4028235e38f : v.y * 0.125f;
            mx = fmaxf(mx, fmaxf(v.x, v.y));
        }
        if (lam == 0) {
            float v = __half2float(sS[li * 520 + 512]) * 0.125f;
            if (mrow[512]) v = -3.4028235e38f;
            mx = fmaxf(mx, v);
        }
#pragma unroll
        for (int o = 16; o > 0; o >>= 1) mx = fmaxf(mx, __shfl_xor_sync(0xffffffffu, mx, o));
        float s = 0.f;
        for (int j2 = lam; j2 < 256; j2 += 32) {
            float2 v = __half22float2(srow2[j2]);
            v.x = mrow[2 * j2]     ? -3.4028235e38f : v.x * 0.125f;
            v.y = mrow[2 * j2 + 1] ? -3.4028235e38f : v.y * 0.125f;
            float e0 = __expf(v.x - mx), e1 = __expf(v.y - mx);
            srow2[j2] = __floats2half2_rn(e0, e1);
            s += e0 + e1;
        }
        if (lam == 0) {
            float v = __half2float(sS[li * 520 + 512]) * 0.125f;
            if (mrow[512]) v = -3.4028235e38f;
            float e = __expf(v - mx);
            sS[li * 520 + 512] = __float2half_rn(e);
            s += e;
        }
#pragma unroll
        for (int o = 16; o > 0; o >>= 1) s += __shfl_xor_sync(0xffffffffu, s, o);
        if (lam == 0) sSum[li] = s;
    }
    __syncthreads();

    // ===================== AV phase (tf32) =====================
    float O[4][4];
#pragma unroll
    for (int nt = 0; nt < 4; nt++)
#pragma unroll
        for (int r = 0; r < 4; r++) O[nt][r] = 0.f;

    for (int jt = 0; jt < 9; jt++) {
        int j0 = jt * 64;
        __syncthreads();
        // stage V_j as tf32 B-frags: k-dim = key, n-dim = hd
#pragma unroll
        for (int u = 0; u < 4; u++) {
            int key = (t >> 4) + u * 16;
            int hd4 = (t & 15) * 4;
            int gk = j0 + key;
            float4 kv = make_float4(0.f, 0.f, 0.f, 0.f);
            if (gk < NL) kv = *(const float4*)(Vg + (size_t)gk * 64 + hd4);
            int ks2 = key >> 3, kk = key & 7;
            unsigned base = ks2 * 520 + (hd4 >> 3) * 64 + (hd4 & 7) * 8
                          + (kk & 3) * 2 + (kk >> 2);
            sKG[base + 0]  = cvt_tf32(kv.x);
            sKG[base + 8]  = cvt_tf32(kv.y);
            sKG[base + 16] = cvt_tf32(kv.z);
            sKG[base + 24] = cvt_tf32(kv.w);
        }
        __syncthreads();
#pragma unroll
        for (int ks = 0; ks < 8; ks++) {
            int kc = j0 + ks * 8 + (lam & 3);
            float a0 = __half2float(sS[gr0 * 520 + kc]);
            float a1 = __half2float(sS[(gr0 + 8) * 520 + kc]);
            float a2 = __half2float(sS[gr0 * 520 + kc + 4]);
            float a3 = __half2float(sS[(gr0 + 8) * 520 + kc + 4]);
            uint4 av = make_uint4(cvt_tf32(a0), cvt_tf32(a1), cvt_tf32(a2), cvt_tf32(a3));
#pragma unroll
            for (int nt = 0; nt < 4; nt++) {
                uint2 bv = *(const uint2*)&sKG[ks * 520 + (ch * 4 + nt) * 64 + lam * 2];
                mma_tf32(O[nt], av, bv);
            }
        }
    }

    float l0 = 1.f / sSum[gr0];
    float l1 = 1.f / sSum[gr0 + 8];
#pragma unroll
    for (int nt = 0; nt < 4; nt++) {
        int hd = ch * 32 + nt * 8 + 2 * (lam & 3);
        if (r0g < NL) {
            float2 st = make_float2(O[nt][0] * l0, O[nt][1] * l0);
            *(float2*)&ctx[((size_t)b * NL + r0g) * ND + h * 64 + hd] = st;
        }
        if (r1g < NL) {
            float2 st = make_float2(O[nt][2] * l1, O[nt][3] * l1);
            *(float2*)&ctx[((size_t)b * NL + r1g) * ND + h * 64 + hd] = st;
        }
    }
}

// ---------------------------------------------------------------------------
extern "C" void kernel_launch(void* const* d_in, const int* in_sizes, int n_in,
                              void* d_out, int out_size)
{
    const float* x     = (const float*)d_in[0];
    const float* pe    = (const float*)d_in[1];
    const unsigned char* mask = (const unsigned char*)d_in[2];
    const float* qkv_w = (const float*)d_in[3];
    const float* qkv_b = (const float*)d_in[4];
    const float* pos_w = (const float*)d_in[5];
    const float* pos_b = (const float*)d_in[6];
    const float* out_w = (const float*)d_in[7];
    const float* out_b = (const float*)d_in[8];
    const float* cbias = (const float*)d_in[9];
    const float* pbias = (const float*)d_in[10];
    float* out = (float*)d_out;

    float* ctxp = nullptr;
    cudaGetSymbolAddress((void**)&ctxp, g_CTX);

    const int M1 = NB * NL;                 // 8208
    const int ATTN_SMEM = 108160;
    cudaFuncSetAttribute(attn_mma, cudaFuncAttributeMaxDynamicSharedMemorySize, ATTN_SMEM);

    dim3 blk(256);
    gemm_tf32<0><<<dim3(3072 / 128, (M1 + 127) / 128), blk>>>(
        x, qkv_w, M1, 3072, qkv_b, cbias, pbias, nullptr);
    gemm_tf32<1><<<dim3(16384 / 128, 1024 / 128), blk>>>(
        pos_w, pe, 1024, 16384, pos_b, nullptr, nullptr, nullptr);
    attn_mma<<<dim3(9, NH, NB), blk, ATTN_SMEM>>>(mask, ctxp);
    gemm_tf32<2><<<dim3(1024 / 128, (M1 + 127) / 128), blk>>>(
        ctxp, out_w, M1, 1024, out_b, nullptr, nullptr, out);
}

// round 7
// speedup vs baseline: 1.1234x; 1.1234x over previous
#include <cuda_runtime.h>
#include <cuda_fp16.h>
#include <math.h>

#define NB 16
#define NH 16
#define NHD 64
#define ND 1024
#define NL 513
#define NP 1024

// Scratch (allocation-free rule: __device__ globals)
__device__ float g_QC[NB*NH*NL*NHD];   // q + content_bias, [b,h,l,hd]
__device__ float g_QP[NB*NH*NL*NHD];   // q + position_bias
__device__ float g_Kt[NB*NH*NL*NHD];   // k, [b,h,l,hd]
__device__ float g_Vt[NB*NH*NL*NHD];   // v, [b,h,l,hd]
__device__ float g_PT[NB*NH*NP*NHD];   // pos projected, transposed: [b,h,p,hd]
__device__ float g_CTX[NB*NL*ND];      // attention output, [b,l,h*64+hd]

__device__ __forceinline__ unsigned cvt_tf32(float f) {
    unsigned u;
    asm("cvt.rna.tf32.f32 %0, %1;" : "=r"(u) : "f"(f));
    return u;
}

__device__ __forceinline__ void mma_tf32(float* d, const uint4& a, const uint2& b) {
    asm volatile(
        "mma.sync.aligned.m16n8k8.row.col.f32.tf32.tf32.f32 "
        "{%0,%1,%2,%3}, {%4,%5,%6,%7}, {%8,%9}, {%0,%1,%2,%3};"
        : "+f"(d[0]), "+f"(d[1]), "+f"(d[2]), "+f"(d[3])
        : "r"(a.x), "r"(a.y), "r"(a.z), "r"(a.w), "r"(b.x), "r"(b.y));
}

__device__ __forceinline__ void mma_f16(float* d, const uint4& a, const uint2& b) {
    asm volatile(
        "mma.sync.aligned.m16n8k16.row.col.f32.f16.f16.f32 "
        "{%0,%1,%2,%3}, {%4,%5,%6,%7}, {%8,%9}, {%0,%1,%2,%3};"
        : "+f"(d[0]), "+f"(d[1]), "+f"(d[2]), "+f"(d[3])
        : "r"(a.x), "r"(a.y), "r"(a.z), "r"(a.w), "r"(b.x), "r"(b.y));
}

__device__ __forceinline__ unsigned pkh2(float x, float y) {
    __half2 h = __floats2half2_rn(x, y);
    return *(unsigned*)&h;
}

// ---------------------------------------------------------------------------
// tf32 tensor-core GEMM, single-buffer BK=32 (proven R5 config):
// C = A @ Bw^T (+epilogue). 256 thr / 8 warps (2M x 4N of 64x32 tiles).
// Smem stores mma fragments directly; conflict-free LDS.128/LDS.64 reads.
// ---------------------------------------------------------------------------
template<int EPI>
__global__ void __launch_bounds__(256, 2)
gemm_tf32(const float* __restrict__ A, const float* __restrict__ Bw,
          int M, int N,
          const float* __restrict__ bias,
          const float* __restrict__ cbias, const float* __restrict__ pbias,
          float* __restrict__ out)
{
    const int K = 1024;
    __shared__ unsigned sA[4240];
    __shared__ unsigned sB[4104];

    int t    = threadIdx.x;
    int lane = t & 31, w = t >> 5;
    int warpM = w & 1, warpN = w >> 1;
    int m0 = blockIdx.y * 128, n0 = blockIdx.x * 128;

    int lrow = t >> 3;
    int lkq  = t & 7;
    int ksL  = lkq >> 1;
    int frp  = lkq & 1;

    float acc[4][4][4];
#pragma unroll
    for (int i = 0; i < 4; i++)
#pragma unroll
        for (int j = 0; j < 4; j++)
#pragma unroll
            for (int r = 0; r < 4; r++) acc[i][j][r] = 0.f;

    for (int kt = 0; kt < K; kt += 32) {
#pragma unroll
        for (int u = 0; u < 4; u++) {
            int ml = lrow + u * 32;
            int gm = m0 + ml;
            float4 va = make_float4(0.f, 0.f, 0.f, 0.f);
            if (gm < M) va = *(const float4*)(A + (size_t)gm * K + kt + lkq * 4);
            int mt = ml >> 4, mp = ml & 15;
            int fr = frp * 2 + (mp >> 3);
            unsigned ba = ksL * 1060 + mt * 132 + (mp & 7) * 16 + fr;
            sA[ba + 0]  = cvt_tf32(va.x);
            sA[ba + 4]  = cvt_tf32(va.y);
            sA[ba + 8]  = cvt_tf32(va.z);
            sA[ba + 12] = cvt_tf32(va.w);

            int nl = ml;
            float4 vb = *(const float4*)(Bw + (size_t)(n0 + nl) * K + kt + lkq * 4);
            int nt = nl >> 3, np = nl & 7;
            unsigned bb = ksL * 1026 + nt * 64 + np * 8 + frp;
            sB[bb + 0] = cvt_tf32(vb.x);
            sB[bb + 2] = cvt_tf32(vb.y);
            sB[bb + 4] = cvt_tf32(vb.z);
            sB[bb + 6] = cvt_tf32(vb.w);
        }
        __syncthreads();

#pragma unroll
        for (int ks = 0; ks < 4; ks++) {
            uint4 av[4];
            uint2 bv[4];
#pragma unroll
            for (int i = 0; i < 4; i++)
                av[i] = *(const uint4*)&sA[ks * 1060 + (warpM * 4 + i) * 132 + lane * 4];
#pragma unroll
            for (int j = 0; j < 4; j++)
                bv[j] = *(const uint2*)&sB[ks * 1026 + (warpN * 4 + j) * 64 + lane * 2];
#pragma unroll
            for (int i = 0; i < 4; i++)
#pragma unroll
                for (int j = 0; j < 4; j++)
                    mma_tf32(acc[i][j], av[i], bv[j]);
        }
        __syncthreads();
    }

    int mb = m0 + warpM * 64 + (lane >> 2);
    int nb = n0 + warpN * 32 + (lane & 3) * 2;
#pragma unroll
    for (int i = 0; i < 4; i++) {
#pragma unroll
        for (int rr = 0; rr < 2; rr++) {
            int m = mb + i * 16 + rr * 8;
            if (m >= M) continue;
            if (EPI == 0) {
                int b_ = m / NL, l = m - b_ * NL;
#pragma unroll
                for (int j = 0; j < 4; j++) {
                    int n = nb + j * 8;            // even; pair (n, n+1) same part/head
                    float v0 = acc[i][j][rr * 2 + 0] + bias[n];
                    float v1 = acc[i][j][rr * 2 + 1] + bias[n + 1];
                    int part = n >> 10, c1 = n & 1023;
                    int hh = c1 >> 6, hd = c1 & 63;
                    size_t o = ((((size_t)b_ * NH + hh) * NL + l) << 6) + hd;
                    if (part == 0) {
                        *(float2*)&g_QC[o] = make_float2(v0 + cbias[c1], v1 + cbias[c1 + 1]);
                        *(float2*)&g_QP[o] = make_float2(v0 + pbias[c1], v1 + pbias[c1 + 1]);
                    } else if (part == 1) {
                        *(float2*)&g_Kt[o] = make_float2(v0, v1);
                    } else {
                        *(float2*)&g_Vt[o] = make_float2(v0, v1);
                    }
                }
            } else if (EPI == 1) {
                float bm = bias[m];
#pragma unroll
                for (int j = 0; j < 4; j++) {
                    int n = nb + j * 8;
                    float v0 = acc[i][j][rr * 2 + 0] + bm;
                    float v1 = acc[i][j][rr * 2 + 1] + bm;
                    int bh = n >> 6, hd = n & 63;
                    *(float2*)&g_PT[((((size_t)bh) << 10) + m) * 64 + hd] = make_float2(v0, v1);
                }
            } else {
#pragma unroll
                for (int j = 0; j < 4; j++) {
                    int n = nb + j * 8;
                    float2 st;
                    st.x = acc[i][j][rr * 2 + 0] + bias[n];
                    st.y = acc[i][j][rr * 2 + 1] + bias[n + 1];
                    *(float2*)(out + (size_t)m * ND + n) = st;
                }
            }
        }
    }
}

// ---------------------------------------------------------------------------
// Tensor-core fused attention (R6 version — band-pruned G, float4 P staging,
// half2 softmax). CTA = (i-tile of 64 q, one b,h), 256 thr/8 warps.
// smem 108,160B -> 2 CTAs/SM.
// ---------------------------------------------------------------------------
__global__ void __launch_bounds__(256, 2)
attn_mma(const unsigned char* __restrict__ mask, float* __restrict__ ctx)
{
    extern __shared__ char smraw[];
    __half*   sS  = (__half*)smraw;                   // [64][520] + 64 pad halves
    unsigned* sKG = (unsigned*)(smraw + 66688);       // K/V tf32 frags | G f16 (16,640B)
    unsigned* sP  = (unsigned*)(smraw + 83328);       // P band f16 frags (16,384B)
    unsigned* sQP = (unsigned*)(smraw + 99712);       // QP f16 A-frags (8,192B)
    float*    sSum= (float*)(smraw + 107904);         // [64]
    __half*   sG  = (__half*)sKG;                     // G view: [64][130] halves

    int t = threadIdx.x, lam = t & 31, w = t >> 5;
    int rg = w & 3, ch = w >> 2;
    int it = blockIdx.x, h = blockIdx.y, b = blockIdx.z;
    int i0 = it * 64;
    size_t bh = (size_t)b * NH + h;
    const float* QCg = g_QC + bh * NL * NHD;
    const float* QPg = g_QP + bh * NL * NHD;
    const float* Kg  = g_Kt + bh * NL * NHD;
    const float* Vg  = g_Vt + bh * NL * NHD;
    const float* Pg  = g_PT + bh * NP * NHD;

    // zero sS (incl. pads)
    for (int idx = t; idx < 16672; idx += 256) ((unsigned*)sS)[idx] = 0u;

    int gr0 = rg * 16 + (lam >> 2);
    int r0g = i0 + gr0, r1g = r0g + 8;
    int gt0 = 6 - 2 * rg;      // first G n8-tile needed by this row group

    // QC A-frags (tf32) in registers: 8 ksteps
    uint4 qcf[8];
#pragma unroll
    for (int ks = 0; ks < 8; ks++) {
        int c0 = ks * 8 + (lam & 3);
        float a0 = (r0g < NL) ? QCg[r0g * 64 + c0]     : 0.f;
        float a1 = (r1g < NL) ? QCg[r1g * 64 + c0]     : 0.f;
        float a2 = (r0g < NL) ? QCg[r0g * 64 + c0 + 4] : 0.f;
        float a3 = (r1g < NL) ? QCg[r1g * 64 + c0 + 4] : 0.f;
        qcf[ks] = make_uint4(cvt_tf32(a0), cvt_tf32(a1), cvt_tf32(a2), cvt_tf32(a3));
    }

    // stage QP f16 A-frags
    {
        int rgs = w & 3;
        int rs0 = i0 + rgs * 16 + (lam >> 2), rs1 = rs0 + 8;
#pragma unroll
        for (int si = 0; si < 2; si++) {
            int s = (w >> 2) * 2 + si;
            int k2 = s * 16 + 2 * (lam & 3);
            float q00 = 0, q01 = 0, q10 = 0, q11 = 0, q02 = 0, q03 = 0, q12 = 0, q13 = 0;
            if (rs0 < NL) {
                q00 = QPg[rs0 * 64 + k2];     q01 = QPg[rs0 * 64 + k2 + 1];
                q02 = QPg[rs0 * 64 + k2 + 8]; q03 = QPg[rs0 * 64 + k2 + 9];
            }
            if (rs1 < NL) {
                q10 = QPg[rs1 * 64 + k2];     q11 = QPg[rs1 * 64 + k2 + 1];
                q12 = QPg[rs1 * 64 + k2 + 8]; q13 = QPg[rs1 * 64 + k2 + 9];
            }
            uint4 v = make_uint4(pkh2(q00, q01), pkh2(q10, q11),
                                 pkh2(q02, q03), pkh2(q12, q13));
            *(uint4*)&sQP[(rgs * 4 + s) * 128 + lam * 4] = v;
        }
    }

    // ===================== score phase =====================
    for (int jt = 0; jt < 9; jt++) {
        int j0 = jt * 64;
        __syncthreads();
        // stage K_j as tf32 B-frags (k-dim = hd, n-dim = key)
#pragma unroll
        for (int u = 0; u < 4; u++) {
            int key = (t >> 4) + u * 16;
            int hd4 = (t & 15) * 4;
            int gk = j0 + key;
            float4 kv = make_float4(0.f, 0.f, 0.f, 0.f);
            if (gk < NL) kv = *(const float4*)(Kg + (size_t)gk * 64 + hd4);
            int ks = hd4 >> 3, khigh = (hd4 & 7) >> 2;
            unsigned base = ks * 520 + (key >> 3) * 64 + (key & 7) * 8 + khigh;
            sKG[base + 0] = cvt_tf32(kv.x);
            sKG[base + 2] = cvt_tf32(kv.y);
            sKG[base + 4] = cvt_tf32(kv.z);
            sKG[base + 6] = cvt_tf32(kv.w);
        }
        // stage P band (128 rows x 64 hd) as f16 B-frags, float4 sources
        int pbase = j0 - i0 + 449;
#pragma unroll
        for (int u = 0; u < 8; u++) {
            int idx = u * 256 + t;
            int c = idx >> 4, d4 = (idx & 15) * 4;
            int p = pbase + c;
            unsigned h0 = 0u, h1 = 0u;
            if ((unsigned)p < (unsigned)NP) {
                float4 pv = *(const float4*)(Pg + (size_t)p * 64 + d4);
                h0 = pkh2(pv.x, pv.y);
                h1 = pkh2(pv.z, pv.w);
            }
            int step = d4 >> 4, d16 = d4 & 15;
            unsigned a0 = step * 1024 + (c >> 3) * 64 + ((c & 7) * 4 + ((d16 & 7) >> 1)) * 2 + (d16 >> 3);
            sP[a0]     = h0;
            sP[a0 + 2] = h1;
        }
        __syncthreads();

        // content MMA (tf32): 4 n8-tiles
        float C[4][4];
#pragma unroll
        for (int nt = 0; nt < 4; nt++)
#pragma unroll
            for (int r = 0; r < 4; r++) C[nt][r] = 0.f;
#pragma unroll
        for (int ks = 0; ks < 8; ks++) {
            uint4 av = qcf[ks];
#pragma unroll
            for (int nt = 0; nt < 4; nt++) {
                uint2 bv = *(const uint2*)&sKG[ks * 520 + (ch * 4 + nt) * 64 + lam * 2];
                mma_tf32(C[nt], av, bv);
            }
        }
        // G MMA (f16): only the 10 band tiles this row group needs (5 per ch)
        float G[5][4];
#pragma unroll
        for (int nt = 0; nt < 5; nt++)
#pragma unroll
            for (int r = 0; r < 4; r++) G[nt][r] = 0.f;
#pragma unroll
        for (int s = 0; s < 4; s++) {
            uint4 af = *(const uint4*)&sQP[(rg * 4 + s) * 128 + lam * 4];
#pragma unroll
            for (int nt = 0; nt < 5; nt++) {
                int tg = gt0 + ch * 5 + nt;
                uint2 bv = *(const uint2*)&sP[s * 1024 + tg * 64 + lam * 2];
                mma_f16(G[nt], af, bv);
            }
        }
        __syncthreads();   // content reads of sKG done before G overwrite
#pragma unroll
        for (int nt = 0; nt < 5; nt++) {
            int c0 = (gt0 + ch * 5 + nt) * 8 + 2 * (lam & 3);
            *(__half2*)&sG[gr0 * 130 + c0]       = __floats2half2_rn(G[nt][0], G[nt][1]);
            *(__half2*)&sG[(gr0 + 8) * 130 + c0] = __floats2half2_rn(G[nt][2], G[nt][3]);
        }
        __syncthreads();   // G visible
#pragma unroll
        for (int nt = 0; nt < 4; nt++) {
            int jjb = ch * 32 + nt * 8 + 2 * (lam & 3);
            float s0 = C[nt][0] + __half2float(sG[gr0 * 130 + (jjb - gr0 + 63)]);
            float s1 = C[nt][1] + __half2float(sG[gr0 * 130 + (jjb + 1 - gr0 + 63)]);
            float s2 = C[nt][2] + __half2float(sG[(gr0 + 8) * 130 + (jjb - gr0 - 8 + 63)]);
            float s3 = C[nt][3] + __half2float(sG[(gr0 + 8) * 130 + (jjb + 1 - gr0 - 8 + 63)]);
            if (j0 + jjb < NL) {
                *(__half2*)&sS[gr0 * 520 + j0 + jjb]       = __floats2half2_rn(s0, s1);
                *(__half2*)&sS[(gr0 + 8) * 520 + j0 + jjb] = __floats2half2_rn(s2, s3);
            }
        }
    }
    __syncthreads();

    // ===================== softmax (warp per row, half2) =====================
    for (int li = w * 8; li < w * 8 + 8; li++) {
        int i = i0 + li;
        if (i >= NL) { if (lam == 0) sSum[li] = 1.f; continue; }
        const unsigned char* mrow = mask + ((size_t)b * NL + i) * NL;
        __half2* srow2 = (__half2*)&sS[li * 520];
        float mx = -3.4028235e38f;
        for (int j2 = lam; j2 < 256; j2 += 32) {
            float2 v = __half22float2(srow2[j2]);
            v.x = mrow[2 * j2]     ? -3.4028235e38f : v.x * 0.125f;
            v.y = mrow[2 * j2 + 1] ? -3.4028235e38f : v.y * 0.125f;
            mx = fmaxf(mx, fmaxf(v.x, v.y));
        }
        if (lam == 0) {
            float v = __half2float(sS[li * 520 + 512]) * 0.125f;
            if (mrow[512]) v = -3.4028235e38f;
            mx = fmaxf(mx, v);
        }
#pragma unroll
        for (int o = 16; o > 0; o >>= 1) mx = fmaxf(mx, __shfl_xor_sync(0xffffffffu, mx, o));
        float s = 0.f;
        for (int j2 = lam; j2 < 256; j2 += 32) {
            float2 v = __half22float2(srow2[j2]);
            v.x = mrow[2 * j2]     ? -3.4028235e38f : v.x * 0.125f;
            v.y = mrow[2 * j2 + 1] ? -3.4028235e38f : v.y * 0.125f;
            float e0 = __expf(v.x - mx), e1 = __expf(v.y - mx);
            srow2[j2] = __floats2half2_rn(e0, e1);
            s += e0 + e1;
        }
        if (lam == 0) {
            float v = __half2float(sS[li * 520 + 512]) * 0.125f;
            if (mrow[512]) v = -3.4028235e38f;
            float e = __expf(v - mx);
            sS[li * 520 + 512] = __float2half_rn(e);
            s += e;
        }
#pragma unroll
        for (int o = 16; o > 0; o >>= 1) s += __shfl_xor_sync(0xffffffffu, s, o);
        if (lam == 0) sSum[li] = s;
    }
    __syncthreads();

    // ===================== AV phase (tf32) =====================
    float O[4][4];
#pragma unroll
    for (int nt = 0; nt < 4; nt++)
#pragma unroll
        for (int r = 0; r < 4; r++) O[nt][r] = 0.f;

    for (int jt = 0; jt < 9; jt++) {
        int j0 = jt * 64;
        __syncthreads();
        // stage V_j as tf32 B-frags: k-dim = key, n-dim = hd
#pragma unroll
        for (int u = 0; u < 4; u++) {
            int key = (t >> 4) + u * 16;
            int hd4 = (t & 15) * 4;
            int gk = j0 + key;
            float4 kv = make_float4(0.f, 0.f, 0.f, 0.f);
            if (gk < NL) kv = *(const float4*)(Vg + (size_t)gk * 64 + hd4);
            int ks2 = key >> 3, kk = key & 7;
            unsigned base = ks2 * 520 + (hd4 >> 3) * 64 + (hd4 & 7) * 8
                          + (kk & 3) * 2 + (kk >> 2);
            sKG[base + 0]  = cvt_tf32(kv.x);
            sKG[base + 8]  = cvt_tf32(kv.y);
            sKG[base + 16] = cvt_tf32(kv.z);
            sKG[base + 24] = cvt_tf32(kv.w);
        }
        __syncthreads();
#pragma unroll
        for (int ks = 0; ks < 8; ks++) {
            int kc = j0 + ks * 8 + (lam & 3);
            float a0 = __half2float(sS[gr0 * 520 + kc]);
            float a1 = __half2float(sS[(gr0 + 8) * 520 + kc]);
            float a2 = __half2float(sS[gr0 * 520 + kc + 4]);
            float a3 = __half2float(sS[(gr0 + 8) * 520 + kc + 4]);
            uint4 av = make_uint4(cvt_tf32(a0), cvt_tf32(a1), cvt_tf32(a2), cvt_tf32(a3));
#pragma unroll
            for (int nt = 0; nt < 4; nt++) {
                uint2 bv = *(const uint2*)&sKG[ks * 520 + (ch * 4 + nt) * 64 + lam * 2];
                mma_tf32(O[nt], av, bv);
            }
        }
    }

    float l0 = 1.f / sSum[gr0];
    float l1 = 1.f / sSum[gr0 + 8];
#pragma unroll
    for (int nt = 0; nt < 4; nt++) {
        int hd = ch * 32 + nt * 8 + 2 * (lam & 3);
        if (r0g < NL) {
            float2 st = make_float2(O[nt][0] * l0, O[nt][1] * l0);
            *(float2*)&ctx[((size_t)b * NL + r0g) * ND + h * 64 + hd] = st;
        }
        if (r1g < NL) {
            float2 st = make_float2(O[nt][2] * l1, O[nt][3] * l1);
            *(float2*)&ctx[((size_t)b * NL + r1g) * ND + h * 64 + hd] = st;
        }
    }
}

// ---------------------------------------------------------------------------
extern "C" void kernel_launch(void* const* d_in, const int* in_sizes, int n_in,
                              void* d_out, int out_size)
{
    const float* x     = (const float*)d_in[0];
    const float* pe    = (const float*)d_in[1];
    const unsigned char* mask = (const unsigned char*)d_in[2];
    const float* qkv_w = (const float*)d_in[3];
    const float* qkv_b = (const float*)d_in[4];
    const float* pos_w = (const float*)d_in[5];
    const float* pos_b = (const float*)d_in[6];
    const float* out_w = (const float*)d_in[7];
    const float* out_b = (const float*)d_in[8];
    const float* cbias = (const float*)d_in[9];
    const float* pbias = (const float*)d_in[10];
    float* out = (float*)d_out;

    float* ctxp = nullptr;
    cudaGetSymbolAddress((void**)&ctxp, g_CTX);

    const int M1 = NB * NL;                 // 8208
    const int ATTN_SMEM = 108160;
    cudaFuncSetAttribute(attn_mma, cudaFuncAttributeMaxDynamicSharedMemorySize, ATTN_SMEM);

    dim3 blk(256);
    gemm_tf32<0><<<dim3(3072 / 128, (M1 + 127) / 128), blk>>>(
        x, qkv_w, M1, 3072, qkv_b, cbias, pbias, nullptr);
    gemm_tf32<1><<<dim3(16384 / 128, 1024 / 128), blk>>>(
        pos_w, pe, 1024, 16384, pos_b, nullptr, nullptr, nullptr);
    attn_mma<<<dim3(9, NH, NB), blk, ATTN_SMEM>>>(mask, ctxp);
    gemm_tf32<2><<<dim3(1024 / 128, (M1 + 127) / 128), blk>>>(
        ctxp, out_w, M1, 1024, out_b, nullptr, nullptr, out);
}

// round 8
// speedup vs baseline: 1.1771x; 1.0478x over previous
#include <cuda_runtime.h>
#include <cuda_fp16.h>
#include <math.h>

#define NB 16
#define NH 16
#define NHD 64
#define ND 1024
#define NL 513
#define NP 1024

// Scratch (allocation-free rule: __device__ globals)
__device__ float g_QC[NB*NH*NL*NHD];   // q + content_bias, [b,h,l,hd]
__device__ float g_QP[NB*NH*NL*NHD];   // q + position_bias
__device__ float g_Kt[NB*NH*NL*NHD];   // k, [b,h,l,hd]
__device__ float g_Vt[NB*NH*NL*NHD];   // v, [b,h,l,hd]
__device__ float g_PT[NB*NH*NP*NHD];   // pos projected, transposed: [b,h,p,hd]
__device__ float g_CTX[NB*NL*ND];      // attention output, [b,l,h*64+hd]

__device__ __forceinline__ unsigned cvt_tf32(float f) {
    unsigned u;
    asm("cvt.rna.tf32.f32 %0, %1;" : "=r"(u) : "f"(f));
    return u;
}

__device__ __forceinline__ void mma_tf32(float* d, const uint4& a, const uint2& b) {
    asm volatile(
        "mma.sync.aligned.m16n8k8.row.col.f32.tf32.tf32.f32 "
        "{%0,%1,%2,%3}, {%4,%5,%6,%7}, {%8,%9}, {%0,%1,%2,%3};"
        : "+f"(d[0]), "+f"(d[1]), "+f"(d[2]), "+f"(d[3])
        : "r"(a.x), "r"(a.y), "r"(a.z), "r"(a.w), "r"(b.x), "r"(b.y));
}

__device__ __forceinline__ void mma_f16(float* d, const uint4& a, const uint2& b) {
    asm volatile(
        "mma.sync.aligned.m16n8k16.row.col.f32.f16.f16.f32 "
        "{%0,%1,%2,%3}, {%4,%5,%6,%7}, {%8,%9}, {%0,%1,%2,%3};"
        : "+f"(d[0]), "+f"(d[1]), "+f"(d[2]), "+f"(d[3])
        : "r"(a.x), "r"(a.y), "r"(a.z), "r"(a.w), "r"(b.x), "r"(b.y));
}

__device__ __forceinline__ unsigned pkh2(float x, float y) {
    __half2 h = __floats2half2_rn(x, y);
    return *(unsigned*)&h;
}

// ---------------------------------------------------------------------------
// tf32 tensor-core GEMM, double-buffered BK=32, ONE barrier per chunk:
//   GLOAD(c+1) -> regs; MMA(buf cur); SSTORE(buf 1-cur); bar.
// 256 thr / 8 warps (2M x 4N of 64x32 tiles). Dynamic smem 66,752 B.
// ---------------------------------------------------------------------------
template<int EPI>
__global__ void __launch_bounds__(256, 2)
gemm_tf32(const float* __restrict__ A, const float* __restrict__ Bw,
          int M, int N,
          const float* __restrict__ bias,
          const float* __restrict__ cbias, const float* __restrict__ pbias,
          float* __restrict__ out)
{
    const int K = 1024;
    extern __shared__ unsigned gsm[];
    unsigned* sA = gsm;            // 2 x 4240
    unsigned* sB = gsm + 2 * 4240; // 2 x 4104

    int t    = threadIdx.x;
    int lane = t & 31, w = t >> 5;
    int warpM = w & 1, warpN = w >> 1;
    int m0 = blockIdx.y * 128, n0 = blockIdx.x * 128;

    int lrow = t >> 3;        // 0..31
    int lkq  = t & 7;
    int ksL  = lkq >> 1;
    int frp  = lkq & 1;

    // precomputed fragment staging addresses
    unsigned baA[4], baB[4];
#pragma unroll
    for (int u = 0; u < 4; u++) {
        int ml = lrow + u * 32;
        int mt = ml >> 4, mp = ml & 15;
        baA[u] = ksL * 1060 + mt * 132 + (mp & 7) * 16 + frp * 2 + (mp >> 3);
        baB[u] = ksL * 1026 + (ml >> 3) * 64 + (ml & 7) * 8 + frp;
    }

    float acc[4][4][4];
#pragma unroll
    for (int i = 0; i < 4; i++)
#pragma unroll
        for (int j = 0; j < 4; j++)
#pragma unroll
            for (int r = 0; r < 4; r++) acc[i][j][r] = 0.f;

    float4 ra[4], rb[4];
    const float4 z4 = make_float4(0.f, 0.f, 0.f, 0.f);

#define GLOAD(KT) {                                                          \
        _Pragma("unroll")                                                    \
        for (int u = 0; u < 4; u++) {                                        \
            int gm = m0 + lrow + u * 32;                                     \
            ra[u] = (gm < M) ? *(const float4*)(A + (size_t)gm * K + (KT) + lkq * 4) : z4; \
            rb[u] = *(const float4*)(Bw + (size_t)(n0 + lrow + u * 32) * K + (KT) + lkq * 4); \
        } }

#define SSTORE(BI) {                                                         \
        _Pragma("unroll")                                                    \
        for (int u = 0; u < 4; u++) {                                        \
            unsigned ba = (BI) * 4240 + baA[u];                              \
            sA[ba + 0]  = cvt_tf32(ra[u].x); sA[ba + 4]  = cvt_tf32(ra[u].y);\
            sA[ba + 8]  = cvt_tf32(ra[u].z); sA[ba + 12] = cvt_tf32(ra[u].w);\
            unsigned bb = (BI) * 4104 + baB[u];                              \
            sB[bb + 0] = cvt_tf32(rb[u].x); sB[bb + 2] = cvt_tf32(rb[u].y);  \
            sB[bb + 4] = cvt_tf32(rb[u].z); sB[bb + 6] = cvt_tf32(rb[u].w);  \
        } }

    GLOAD(0);
    SSTORE(0);
    __syncthreads();

    for (int c = 0; c < 32; c++) {
        int cur = c & 1;
        if (c < 31) GLOAD((c + 1) * 32);
#pragma unroll
        for (int ks = 0; ks < 4; ks++) {
            uint4 av[4];
            uint2 bv[4];
#pragma unroll
            for (int i = 0; i < 4; i++)
                av[i] = *(const uint4*)&sA[cur * 4240 + ks * 1060 + (warpM * 4 + i) * 132 + lane * 4];
#pragma unroll
            for (int j = 0; j < 4; j++)
                bv[j] = *(const uint2*)&sB[cur * 4104 + ks * 1026 + (warpN * 4 + j) * 64 + lane * 2];
#pragma unroll
            for (int i = 0; i < 4; i++)
#pragma unroll
                for (int j = 0; j < 4; j++)
                    mma_tf32(acc[i][j], av[i], bv[j]);
        }
        if (c < 31) SSTORE(1 - cur);
        __syncthreads();
    }
#undef GLOAD
#undef SSTORE

    int mb = m0 + warpM * 64 + (lane >> 2);
    int nb = n0 + warpN * 32 + (lane & 3) * 2;
#pragma unroll
    for (int i = 0; i < 4; i++) {
#pragma unroll
        for (int rr = 0; rr < 2; rr++) {
            int m = mb + i * 16 + rr * 8;
            if (m >= M) continue;
            if (EPI == 0) {
                int b_ = m / NL, l = m - b_ * NL;
#pragma unroll
                for (int j = 0; j < 4; j++) {
                    int n = nb + j * 8;            // even; pair (n, n+1) same part/head
                    float v0 = acc[i][j][rr * 2 + 0] + bias[n];
                    float v1 = acc[i][j][rr * 2 + 1] + bias[n + 1];
                    int part = n >> 10, c1 = n & 1023;
                    int hh = c1 >> 6, hd = c1 & 63;
                    size_t o = ((((size_t)b_ * NH + hh) * NL + l) << 6) + hd;
                    if (part == 0) {
                        *(float2*)&g_QC[o] = make_float2(v0 + cbias[c1], v1 + cbias[c1 + 1]);
                        *(float2*)&g_QP[o] = make_float2(v0 + pbias[c1], v1 + pbias[c1 + 1]);
                    } else if (part == 1) {
                        *(float2*)&g_Kt[o] = make_float2(v0, v1);
                    } else {
                        *(float2*)&g_Vt[o] = make_float2(v0, v1);
                    }
                }
            } else if (EPI == 1) {
                float bm = bias[m];
#pragma unroll
                for (int j = 0; j < 4; j++) {
                    int n = nb + j * 8;
                    float v0 = acc[i][j][rr * 2 + 0] + bm;
                    float v1 = acc[i][j][rr * 2 + 1] + bm;
                    int bh = n >> 6, hd = n & 63;
                    *(float2*)&g_PT[((((size_t)bh) << 10) + m) * 64 + hd] = make_float2(v0, v1);
                }
            } else {
#pragma unroll
                for (int j = 0; j < 4; j++) {
                    int n = nb + j * 8;
                    float2 st;
                    st.x = acc[i][j][rr * 2 + 0] + bias[n];
                    st.y = acc[i][j][rr * 2 + 1] + bias[n + 1];
                    *(float2*)(out + (size_t)m * ND + n) = st;
                }
            }
        }
    }
}

// ---------------------------------------------------------------------------
// Tensor-core fused attention (band-pruned G, float4 P staging, half2 softmax,
// AV V-prefetch). CTA = (i-tile of 64 q, one b,h), 256 thr/8 warps.
// smem 108,160B -> 2 CTAs/SM.
// ---------------------------------------------------------------------------
__global__ void __launch_bounds__(256, 2)
attn_mma(const unsigned char* __restrict__ mask, float* __restrict__ ctx)
{
    extern __shared__ char smraw[];
    __half*   sS  = (__half*)smraw;                   // [64][520] + 64 pad halves
    unsigned* sKG = (unsigned*)(smraw + 66688);       // K/V tf32 frags | G f16 (16,640B)
    unsigned* sP  = (unsigned*)(smraw + 83328);       // P band f16 frags (16,384B)
    unsigned* sQP = (unsigned*)(smraw + 99712);       // QP f16 A-frags (8,192B)
    float*    sSum= (float*)(smraw + 107904);         // [64]
    __half*   sG  = (__half*)sKG;                     // G view: [64][130] halves

    int t = threadIdx.x, lam = t & 31, w = t >> 5;
    int rg = w & 3, ch = w >> 2;
    int it = blockIdx.x, h = blockIdx.y, b = blockIdx.z;
    int i0 = it * 64;
    size_t bh = (size_t)b * NH + h;
    const float* QCg = g_QC + bh * NL * NHD;
    const float* QPg = g_QP + bh * NL * NHD;
    const float* Kg  = g_Kt + bh * NL * NHD;
    const float* Vg  = g_Vt + bh * NL * NHD;
    const float* Pg  = g_PT + bh * NP * NHD;

    // zero sS (incl. pads)
    for (int idx = t; idx < 16672; idx += 256) ((unsigned*)sS)[idx] = 0u;

    int gr0 = rg * 16 + (lam >> 2);
    int r0g = i0 + gr0, r1g = r0g + 8;
    int gt0 = 6 - 2 * rg;      // first G n8-tile needed by this row group

    // V staging thread-constants
    int vkey = t >> 4;         // + u*16
    int vhd4 = (t & 15) * 4;

    // QC A-frags (tf32) in registers: 8 ksteps
    uint4 qcf[8];
#pragma unroll
    for (int ks = 0; ks < 8; ks++) {
        int c0 = ks * 8 + (lam & 3);
        float a0 = (r0g < NL) ? QCg[r0g * 64 + c0]     : 0.f;
        float a1 = (r1g < NL) ? QCg[r1g * 64 + c0]     : 0.f;
        float a2 = (r0g < NL) ? QCg[r0g * 64 + c0 + 4] : 0.f;
        float a3 = (r1g < NL) ? QCg[r1g * 64 + c0 + 4] : 0.f;
        qcf[ks] = make_uint4(cvt_tf32(a0), cvt_tf32(a1), cvt_tf32(a2), cvt_tf32(a3));
    }

    // stage QP f16 A-frags
    {
        int rgs = w & 3;
        int rs0 = i0 + rgs * 16 + (lam >> 2), rs1 = rs0 + 8;
#pragma unroll
        for (int si = 0; si < 2; si++) {
            int s = (w >> 2) * 2 + si;
            int k2 = s * 16 + 2 * (lam & 3);
            float q00 = 0, q01 = 0, q10 = 0, q11 = 0, q02 = 0, q03 = 0, q12 = 0, q13 = 0;
            if (rs0 < NL) {
                q00 = QPg[rs0 * 64 + k2];     q01 = QPg[rs0 * 64 + k2 + 1];
                q02 = QPg[rs0 * 64 + k2 + 8]; q03 = QPg[rs0 * 64 + k2 + 9];
            }
            if (rs1 < NL) {
                q10 = QPg[rs1 * 64 + k2];     q11 = QPg[rs1 * 64 + k2 + 1];
                q12 = QPg[rs1 * 64 + k2 + 8]; q13 = QPg[rs1 * 64 + k2 + 9];
            }
            uint4 v = make_uint4(pkh2(q00, q01), pkh2(q10, q11),
                                 pkh2(q02, q03), pkh2(q12, q13));
            *(uint4*)&sQP[(rgs * 4 + s) * 128 + lam * 4] = v;
        }
    }

    // ===================== score phase =====================
    for (int jt = 0; jt < 9; jt++) {
        int j0 = jt * 64;
        __syncthreads();
        // stage K_j as tf32 B-frags (k-dim = hd, n-dim = key)
#pragma unroll
        for (int u = 0; u < 4; u++) {
            int key = vkey + u * 16;
            int gk = j0 + key;
            float4 kv = make_float4(0.f, 0.f, 0.f, 0.f);
            if (gk < NL) kv = *(const float4*)(Kg + (size_t)gk * 64 + vhd4);
            int ks = vhd4 >> 3, khigh = (vhd4 & 7) >> 2;
            unsigned base = ks * 520 + (key >> 3) * 64 + (key & 7) * 8 + khigh;
            sKG[base + 0] = cvt_tf32(kv.x);
            sKG[base + 2] = cvt_tf32(kv.y);
            sKG[base + 4] = cvt_tf32(kv.z);
            sKG[base + 6] = cvt_tf32(kv.w);
        }
        // stage P band (128 rows x 64 hd) as f16 B-frags, float4 sources
        int pbase = j0 - i0 + 449;
#pragma unroll
        for (int u = 0; u < 8; u++) {
            int idx = u * 256 + t;
            int c = idx >> 4, d4 = (idx & 15) * 4;
            int p = pbase + c;
            unsigned h0 = 0u, h1 = 0u;
            if ((unsigned)p < (unsigned)NP) {
                float4 pv = *(const float4*)(Pg + (size_t)p * 64 + d4);
                h0 = pkh2(pv.x, pv.y);
                h1 = pkh2(pv.z, pv.w);
            }
            int step = d4 >> 4, d16 = d4 & 15;
            unsigned a0 = step * 1024 + (c >> 3) * 64 + ((c & 7) * 4 + ((d16 & 7) >> 1)) * 2 + (d16 >> 3);
            sP[a0]     = h0;
            sP[a0 + 2] = h1;
        }
        __syncthreads();

        // content MMA (tf32): 4 n8-tiles
        float C[4][4];
#pragma unroll
        for (int nt = 0; nt < 4; nt++)
#pragma unroll
            for (int r = 0; r < 4; r++) C[nt][r] = 0.f;
#pragma unroll
        for (int ks = 0; ks < 8; ks++) {
            uint4 av = qcf[ks];
#pragma unroll
            for (int nt = 0; nt < 4; nt++) {
                uint2 bv = *(const uint2*)&sKG[ks * 520 + (ch * 4 + nt) * 64 + lam * 2];
                mma_tf32(C[nt], av, bv);
            }
        }
        // G MMA (f16): only the 10 band tiles this row group needs (5 per ch)
        float G[5][4];
#pragma unroll
        for (int nt = 0; nt < 5; nt++)
#pragma unroll
            for (int r = 0; r < 4; r++) G[nt][r] = 0.f;
#pragma unroll
        for (int s = 0; s < 4; s++) {
            uint4 af = *(const uint4*)&sQP[(rg * 4 + s) * 128 + lam * 4];
#pragma unroll
            for (int nt = 0; nt < 5; nt++) {
                int tg = gt0 + ch * 5 + nt;
                uint2 bv = *(const uint2*)&sP[s * 1024 + tg * 64 + lam * 2];
                mma_f16(G[nt], af, bv);
            }
        }
        __syncthreads();   // content reads of sKG done before G overwrite
#pragma unroll
        for (int nt = 0; nt < 5; nt++) {
            int c0 = (gt0 + ch * 5 + nt) * 8 + 2 * (lam & 3);
            *(__half2*)&sG[gr0 * 130 + c0]       = __floats2half2_rn(G[nt][0], G[nt][1]);
            *(__half2*)&sG[(gr0 + 8) * 130 + c0] = __floats2half2_rn(G[nt][2], G[nt][3]);
        }
        __syncthreads();   // G visible
#pragma unroll
        for (int nt = 0; nt < 4; nt++) {
            int jjb = ch * 32 + nt * 8 + 2 * (lam & 3);
            float s0 = C[nt][0] + __half2float(sG[gr0 * 130 + (jjb - gr0 + 63)]);
            float s1 = C[nt][1] + __half2float(sG[gr0 * 130 + (jjb + 1 - gr0 + 63)]);
            float s2 = C[nt][2] + __half2float(sG[(gr0 + 8) * 130 + (jjb - gr0 - 8 + 63)]);
            float s3 = C[nt][3] + __half2float(sG[(gr0 + 8) * 130 + (jjb + 1 - gr0 - 8 + 63)]);
            if (j0 + jjb < NL) {
                *(__half2*)&sS[gr0 * 520 + j0 + jjb]       = __floats2half2_rn(s0, s1);
                *(__half2*)&sS[(gr0 + 8) * 520 + j0 + jjb] = __floats2half2_rn(s2, s3);
            }
        }
    }
    __syncthreads();

    // prefetch V tile for jt=0 — its latency hides under the softmax phase
    float4 vreg[4];
#define VGLOAD(J0) {                                                         \
        _Pragma("unroll")                                                    \
        for (int u = 0; u < 4; u++) {                                        \
            int gk = (J0) + vkey + u * 16;                                   \
            vreg[u] = (gk < NL) ? *(const float4*)(Vg + (size_t)gk * 64 + vhd4) \
                                : make_float4(0.f, 0.f, 0.f, 0.f);           \
        } }
    VGLOAD(0);

    // ===================== softmax (warp per row, half2) =====================
    for (int li = w * 8; li < w * 8 + 8; li++) {
        int i = i0 + li;
        if (i >= NL) { if (lam == 0) sSum[li] = 1.f; continue; }
        const unsigned char* mrow = mask + ((size_t)b * NL + i) * NL;
        __half2* srow2 = (__half2*)&sS[li * 520];
        float mx = -3.4028235e38f;
        for (int j2 = lam; j2 < 256; j2 += 32) {
            float2 v = __half22float2(srow2[j2]);
            v.x = mrow[2 * j2]     ? -3.4028235e38f : v.x * 0.125f;
            v.y = mrow[2 * j2 + 1] ? -3.4028235e38f : v.y * 0.125f;
            mx = fmaxf(mx, fmaxf(v.x, v.y));
        }
        if (lam == 0) {
            float v = __half2float(sS[li * 520 + 512]) * 0.125f;
            if (mrow[512]) v = -3.4028235e38f;
            mx = fmaxf(mx, v);
        }
#pragma unroll
        for (int o = 16; o > 0; o >>= 1) mx = fmaxf(mx, __shfl_xor_sync(0xffffffffu, mx, o));
        float s = 0.f;
        for (int j2 = lam; j2 < 256; j2 += 32) {
            float2 v = __half22float2(srow2[j2]);
            v.x = mrow[2 * j2]     ? -3.4028235e38f : v.x * 0.125f;
            v.y = mrow[2 * j2 + 1] ? -3.4028235e38f : v.y * 0.125f;
            float e0 = __expf(v.x - mx), e1 = __expf(v.y - mx);
            srow2[j2] = __floats2half2_rn(e0, e1);
            s += e0 + e1;
        }
        if (lam == 0) {
            float v = __half2float(sS[li * 520 + 512]) * 0.125f;
            if (mrow[512]) v = -3.4028235e38f;
            float e = __expf(v - mx);
            sS[li * 520 + 512] = __float2half_rn(e);
            s += e;
        }
#pragma unroll
        for (int o = 16; o > 0; o >>= 1) s += __shfl_xor_sync(0xffffffffu, s, o);
        if (lam == 0) sSum[li] = s;
    }
    __syncthreads();

    // ===================== AV phase (tf32, V prefetched) =====================
    float O[4][4];
#pragma unroll
    for (int nt = 0; nt < 4; nt++)
#pragma unroll
        for (int r = 0; r < 4; r++) O[nt][r] = 0.f;

    for (int jt = 0; jt < 9; jt++) {
        int j0 = jt * 64;
        // store prefetched V as tf32 B-frags: k-dim = key, n-dim = hd
#pragma unroll
        for (int u = 0; u < 4; u++) {
            int key = vkey + u * 16;
            int ks2 = key >> 3, kk = key & 7;
            unsigned base = ks2 * 520 + (vhd4 >> 3) * 64 + (vhd4 & 7) * 8
                          + (kk & 3) * 2 + (kk >> 2);
            sKG[base + 0]  = cvt_tf32(vreg[u].x);
            sKG[base + 8]  = cvt_tf32(vreg[u].y);
            sKG[base + 16] = cvt_tf32(vreg[u].z);
            sKG[base + 24] = cvt_tf32(vreg[u].w);
        }
        __syncthreads();
        if (jt < 8) VGLOAD(j0 + 64);
#pragma unroll
        for (int ks = 0; ks < 8; ks++) {
            int kc = j0 + ks * 8 + (lam & 3);
            float a0 = __half2float(sS[gr0 * 520 + kc]);
            float a1 = __half2float(sS[(gr0 + 8) * 520 + kc]);
            float a2 = __half2float(sS[gr0 * 520 + kc + 4]);
            float a3 = __half2float(sS[(gr0 + 8) * 520 + kc + 4]);
            uint4 av = make_uint4(cvt_tf32(a0), cvt_tf32(a1), cvt_tf32(a2), cvt_tf32(a3));
#pragma unroll
            for (int nt = 0; nt < 4; nt++) {
                uint2 bv = *(const uint2*)&sKG[ks * 520 + (ch * 4 + nt) * 64 + lam * 2];
                mma_tf32(O[nt], av, bv);
            }
        }
        __syncthreads();   // MMA reads of sKG done before next V store
    }
#undef VGLOAD

    float l0 = 1.f / sSum[gr0];
    float l1 = 1.f / sSum[gr0 + 8];
#pragma unroll
    for (int nt = 0; nt < 4; nt++) {
        int hd = ch * 32 + nt * 8 + 2 * (lam & 3);
        if (r0g < NL) {
            float2 st = make_float2(O[nt][0] * l0, O[nt][1] * l0);
            *(float2*)&ctx[((size_t)b * NL + r0g) * ND + h * 64 + hd] = st;
        }
        if (r1g < NL) {
            float2 st = make_float2(O[nt][2] * l1, O[nt][3] * l1);
            *(float2*)&ctx[((size_t)b * NL + r1g) * ND + h * 64 + hd] = st;
        }
    }
}

// ---------------------------------------------------------------------------
extern "C" void kernel_launch(void* const* d_in, const int* in_sizes, int n_in,
                              void* d_out, int out_size)
{
    const float* x     = (const float*)d_in[0];
    const float* pe    = (const float*)d_in[1];
    const unsigned char* mask = (const unsigned char*)d_in[2];
    const float* qkv_w = (const float*)d_in[3];
    const float* qkv_b = (const float*)d_in[4];
    const float* pos_w = (const float*)d_in[5];
    const float* pos_b = (const float*)d_in[6];
    const float* out_w = (const float*)d_in[7];
    const float* out_b = (const float*)d_in[8];
    const float* cbias = (const float*)d_in[9];
    const float* pbias = (const float*)d_in[10];
    float* out = (float*)d_out;

    float* ctxp = nullptr;
    cudaGetSymbolAddress((void**)&ctxp, g_CTX);

    const int M1 = NB * NL;                 // 8208
    const int GEMM_SMEM = 2 * (4240 + 4104) * 4;   // 66,752 B
    const int ATTN_SMEM = 108160;
    cudaFuncSetAttribute(gemm_tf32<0>, cudaFuncAttributeMaxDynamicSharedMemorySize, GEMM_SMEM);
    cudaFuncSetAttribute(gemm_tf32<1>, cudaFuncAttributeMaxDynamicSharedMemorySize, GEMM_SMEM);
    cudaFuncSetAttribute(gemm_tf32<2>, cudaFuncAttributeMaxDynamicSharedMemorySize, GEMM_SMEM);
    cudaFuncSetAttribute(attn_mma, cudaFuncAttributeMaxDynamicSharedMemorySize, ATTN_SMEM);

    dim3 blk(256);
    gemm_tf32<0><<<dim3(3072 / 128, (M1 + 127) / 128), blk, GEMM_SMEM>>>(
        x, qkv_w, M1, 3072, qkv_b, cbias, pbias, nullptr);
    gemm_tf32<1><<<dim3(16384 / 128, 1024 / 128), blk, GEMM_SMEM>>>(
        pos_w, pe, 1024, 16384, pos_b, nullptr, nullptr, nullptr);
    attn_mma<<<dim3(9, NH, NB), blk, ATTN_SMEM>>>(mask, ctxp);
    gemm_tf32<2><<<dim3(1024 / 128, (M1 + 127) / 128), blk, GEMM_SMEM>>>(
        ctxp, out_w, M1, 1024, out_b, nullptr, nullptr, out);
}

// round 9
// speedup vs baseline: 1.3612x; 1.1564x over previous
#include <cuda_runtime.h>
#include <cuda_fp16.h>
#include <math.h>

#define NB 16
#define NH 16
#define NHD 64
#define ND 1024
#define NL 513
#define NP 1024

// Scratch (allocation-free rule: __device__ globals). fp16 intermediates.
__device__ __half g_QCh[NB*NH*NL*NHD];   // q + content_bias, [b,h,l,hd]
__device__ __half g_QPh[NB*NH*NL*NHD];   // q + position_bias
__device__ __half g_Kh [NB*NH*NL*NHD];   // k
__device__ __half g_Vh [NB*NH*NL*NHD];   // v
__device__ __half g_PTh[NB*NH*NP*NHD];   // pos projected, [b,h,p,hd]
__device__ float  g_CTX[NB*NL*ND];       // attention output (fp32)

__device__ __forceinline__ unsigned cvt_tf32(float f) {
    unsigned u;
    asm("cvt.rna.tf32.f32 %0, %1;" : "=r"(u) : "f"(f));
    return u;
}

__device__ __forceinline__ void mma_tf32(float* d, const uint4& a, const uint2& b) {
    asm volatile(
        "mma.sync.aligned.m16n8k8.row.col.f32.tf32.tf32.f32 "
        "{%0,%1,%2,%3}, {%4,%5,%6,%7}, {%8,%9}, {%0,%1,%2,%3};"
        : "+f"(d[0]), "+f"(d[1]), "+f"(d[2]), "+f"(d[3])
        : "r"(a.x), "r"(a.y), "r"(a.z), "r"(a.w), "r"(b.x), "r"(b.y));
}

__device__ __forceinline__ void mma_f16(float* d, const uint4& a, const uint2& b) {
    asm volatile(
        "mma.sync.aligned.m16n8k16.row.col.f32.f16.f16.f32 "
        "{%0,%1,%2,%3}, {%4,%5,%6,%7}, {%8,%9}, {%0,%1,%2,%3};"
        : "+f"(d[0]), "+f"(d[1]), "+f"(d[2]), "+f"(d[3])
        : "r"(a.x), "r"(a.y), "r"(a.z), "r"(a.w), "r"(b.x), "r"(b.y));
}

__device__ __forceinline__ unsigned ldh2(const __half* p) {
    return *(const unsigned*)p;
}
__device__ __forceinline__ unsigned pkh2f(float x, float y) {
    __half2 h = __floats2half2_rn(x, y);
    return *(unsigned*)&h;
}
__device__ __forceinline__ unsigned pkhh(__half x, __half y) {
    __half2 h = __halves2half2(x, y);
    return *(unsigned*)&h;
}

// ---------------------------------------------------------------------------
// tf32 tensor-core GEMM, double-buffered BK=32, ONE barrier per chunk.
// Epilogues store fp16 intermediates (EPI 0/1) or fp32 out (EPI 2).
// ---------------------------------------------------------------------------
template<int EPI>
__global__ void __launch_bounds__(256, 2)
gemm_tf32(const float* __restrict__ A, const float* __restrict__ Bw,
          int M, int N,
          const float* __restrict__ bias,
          const float* __restrict__ cbias, const float* __restrict__ pbias,
          float* __restrict__ out)
{
    const int K = 1024;
    extern __shared__ unsigned gsm[];
    unsigned* sA = gsm;            // 2 x 4240
    unsigned* sB = gsm + 2 * 4240; // 2 x 4104

    int t    = threadIdx.x;
    int lane = t & 31, w = t >> 5;
    int warpM = w & 1, warpN = w >> 1;
    int m0 = blockIdx.y * 128, n0 = blockIdx.x * 128;

    int lrow = t >> 3;        // 0..31
    int lkq  = t & 7;
    int ksL  = lkq >> 1;
    int frp  = lkq & 1;

    unsigned baA[4], baB[4];
#pragma unroll
    for (int u = 0; u < 4; u++) {
        int ml = lrow + u * 32;
        int mt = ml >> 4, mp = ml & 15;
        baA[u] = ksL * 1060 + mt * 132 + (mp & 7) * 16 + frp * 2 + (mp >> 3);
        baB[u] = ksL * 1026 + (ml >> 3) * 64 + (ml & 7) * 8 + frp;
    }

    float acc[4][4][4];
#pragma unroll
    for (int i = 0; i < 4; i++)
#pragma unroll
        for (int j = 0; j < 4; j++)
#pragma unroll
            for (int r = 0; r < 4; r++) acc[i][j][r] = 0.f;

    float4 ra[4], rb[4];
    const float4 z4 = make_float4(0.f, 0.f, 0.f, 0.f);

#define GLOAD(KT) {                                                          \
        _Pragma("unroll")                                                    \
        for (int u = 0; u < 4; u++) {                                        \
            int gm = m0 + lrow + u * 32;                                     \
            ra[u] = (gm < M) ? *(const float4*)(A + (size_t)gm * K + (KT) + lkq * 4) : z4; \
            rb[u] = *(const float4*)(Bw + (size_t)(n0 + lrow + u * 32) * K + (KT) + lkq * 4); \
        } }

#define SSTORE(BI) {                                                         \
        _Pragma("unroll")                                                    \
        for (int u = 0; u < 4; u++) {                                        \
            unsigned ba = (BI) * 4240 + baA[u];                              \
            sA[ba + 0]  = cvt_tf32(ra[u].x); sA[ba + 4]  = cvt_tf32(ra[u].y);\
            sA[ba + 8]  = cvt_tf32(ra[u].z); sA[ba + 12] = cvt_tf32(ra[u].w);\
            unsigned bb = (BI) * 4104 + baB[u];                              \
            sB[bb + 0] = cvt_tf32(rb[u].x); sB[bb + 2] = cvt_tf32(rb[u].y);  \
            sB[bb + 4] = cvt_tf32(rb[u].z); sB[bb + 6] = cvt_tf32(rb[u].w);  \
        } }

    GLOAD(0);
    SSTORE(0);
    __syncthreads();

    for (int c = 0; c < 32; c++) {
        int cur = c & 1;
        if (c < 31) GLOAD((c + 1) * 32);
#pragma unroll
        for (int ks = 0; ks < 4; ks++) {
            uint4 av[4];
            uint2 bv[4];
#pragma unroll
            for (int i = 0; i < 4; i++)
                av[i] = *(const uint4*)&sA[cur * 4240 + ks * 1060 + (warpM * 4 + i) * 132 + lane * 4];
#pragma unroll
            for (int j = 0; j < 4; j++)
                bv[j] = *(const uint2*)&sB[cur * 4104 + ks * 1026 + (warpN * 4 + j) * 64 + lane * 2];
#pragma unroll
            for (int i = 0; i < 4; i++)
#pragma unroll
                for (int j = 0; j < 4; j++)
                    mma_tf32(acc[i][j], av[i], bv[j]);
        }
        if (c < 31) SSTORE(1 - cur);
        __syncthreads();
    }
#undef GLOAD
#undef SSTORE

    int mb = m0 + warpM * 64 + (lane >> 2);
    int nb = n0 + warpN * 32 + (lane & 3) * 2;
#pragma unroll
    for (int i = 0; i < 4; i++) {
#pragma unroll
        for (int rr = 0; rr < 2; rr++) {
            int m = mb + i * 16 + rr * 8;
            if (m >= M) continue;
            if (EPI == 0) {
                int b_ = m / NL, l = m - b_ * NL;
#pragma unroll
                for (int j = 0; j < 4; j++) {
                    int n = nb + j * 8;            // even; pair (n, n+1) same part/head
                    float v0 = acc[i][j][rr * 2 + 0] + bias[n];
                    float v1 = acc[i][j][rr * 2 + 1] + bias[n + 1];
                    int part = n >> 10, c1 = n & 1023;
                    int hh = c1 >> 6, hd = c1 & 63;
                    size_t o = ((((size_t)b_ * NH + hh) * NL + l) << 6) + hd;
                    if (part == 0) {
                        *(unsigned*)&g_QCh[o] = pkh2f(v0 + cbias[c1], v1 + cbias[c1 + 1]);
                        *(unsigned*)&g_QPh[o] = pkh2f(v0 + pbias[c1], v1 + pbias[c1 + 1]);
                    } else if (part == 1) {
                        *(unsigned*)&g_Kh[o] = pkh2f(v0, v1);
                    } else {
                        *(unsigned*)&g_Vh[o] = pkh2f(v0, v1);
                    }
                }
            } else if (EPI == 1) {
                float bm = bias[m];
#pragma unroll
                for (int j = 0; j < 4; j++) {
                    int n = nb + j * 8;
                    float v0 = acc[i][j][rr * 2 + 0] + bm;
                    float v1 = acc[i][j][rr * 2 + 1] + bm;
                    int bh = n >> 6, hd = n & 63;
                    *(unsigned*)&g_PTh[((((size_t)bh) << 10) + m) * 64 + hd] = pkh2f(v0, v1);
                }
            } else {
#pragma unroll
                for (int j = 0; j < 4; j++) {
                    int n = nb + j * 8;
                    float2 st;
                    st.x = acc[i][j][rr * 2 + 0] + bias[n];
                    st.y = acc[i][j][rr * 2 + 1] + bias[n + 1];
                    *(float2*)(out + (size_t)m * ND + n) = st;
                }
            }
        }
    }
}

// ---------------------------------------------------------------------------
// Tensor-core fused attention, all-f16 MMA inputs.
// CTA = (i-tile of 64 q, one b,h), 256 thr / 8 warps: rg=w&3 (16 rows),
// ch=w>>2 (col half). Q frags register-resident. smem 99,968B -> 2 CTAs/SM.
// ---------------------------------------------------------------------------
__global__ void __launch_bounds__(256, 2)
attn_mma(const unsigned char* __restrict__ mask, float* __restrict__ ctx)
{
    extern __shared__ char smraw[];
    __half*   sS  = (__half*)smraw;                   // [64][520] + 64 pad (66,688B)
    unsigned* sKG = (unsigned*)(smraw + 66688);       // K/V f16 frags | G (16,640B)
    unsigned* sP  = (unsigned*)(smraw + 83328);       // P band f16 frags (16,384B)
    float*    sSum= (float*)(smraw + 99712);          // [64]
    __half*   sG  = (__half*)sKG;                     // G view: [64][130] halves

    int t = threadIdx.x, lam = t & 31, w = t >> 5;
    int rg = w & 3, ch = w >> 2;
    int it = blockIdx.x, h = blockIdx.y, b = blockIdx.z;
    int i0 = it * 64;
    size_t bh = (size_t)b * NH + h;
    const __half* QCg = g_QCh + bh * NL * NHD;
    const __half* QPg = g_QPh + bh * NL * NHD;
    const __half* Kg  = g_Kh  + bh * NL * NHD;
    const __half* Vg  = g_Vh  + bh * NL * NHD;
    const __half* Pg  = g_PTh + bh * NP * NHD;

    // zero sS (incl. pads)
    for (int idx = t; idx < 16672; idx += 256) ((unsigned*)sS)[idx] = 0u;

    int gr0 = rg * 16 + (lam >> 2);
    int r0g = i0 + gr0, r1g = r0g + 8;
    int gt0 = 6 - 2 * rg;      // first G n8-tile needed by this row group

    int vkey = t >> 4;         // staging key base
    int vhd4 = (t & 15) * 4;   // staging hd base
    int la2  = (lam & 3) * 2;

    // QC / QP A-frags (f16, m16n8k16): 4 ksteps, register-resident
    uint4 qcf[4], qpf[4];
#pragma unroll
    for (int s = 0; s < 4; s++) {
        int c0 = s * 16 + la2;
        unsigned c00 = (r0g < NL) ? ldh2(QCg + r0g * 64 + c0)     : 0u;
        unsigned c10 = (r1g < NL) ? ldh2(QCg + r1g * 64 + c0)     : 0u;
        unsigned c01 = (r0g < NL) ? ldh2(QCg + r0g * 64 + c0 + 8) : 0u;
        unsigned c11 = (r1g < NL) ? ldh2(QCg + r1g * 64 + c0 + 8) : 0u;
        qcf[s] = make_uint4(c00, c10, c01, c11);
        unsigned p00 = (r0g < NL) ? ldh2(QPg + r0g * 64 + c0)     : 0u;
        unsigned p10 = (r1g < NL) ? ldh2(QPg + r1g * 64 + c0)     : 0u;
        unsigned p01 = (r0g < NL) ? ldh2(QPg + r0g * 64 + c0 + 8) : 0u;
        unsigned p11 = (r1g < NL) ? ldh2(QPg + r1g * 64 + c0 + 8) : 0u;
        qpf[s] = make_uint4(p00, p10, p01, p11);
    }

    // ===================== score phase =====================
    for (int jt = 0; jt < 9; jt++) {
        int j0 = jt * 64;
        __syncthreads();
        // stage K_j as f16 B-frags (k = hd, n = key); 4 steps x 520 uints
        {
            int step = vhd4 >> 4, k16 = vhd4 & 15;
            unsigned boff = step * 520 + ((k16 & 7) >> 1) * 2 + (k16 >> 3);
#pragma unroll
            for (int u = 0; u < 4; u++) {
                int key = vkey + u * 16;
                int gk = j0 + key;
                uint2 kv = make_uint2(0u, 0u);
                if (gk < NL) kv = *(const uint2*)(Kg + (size_t)gk * 64 + vhd4);
                unsigned base = boff + (key >> 3) * 64 + (key & 7) * 8;
                sKG[base]     = kv.x;
                sKG[base + 2] = kv.y;
            }
        }
        // stage P band (128 rows x 64 hd) as f16 B-frags (k = hd, n = c)
        int pbase = j0 - i0 + 449;
#pragma unroll
        for (int u = 0; u < 8; u++) {
            int idx = u * 256 + t;
            int c = idx >> 4, d4 = (idx & 15) * 4;
            int p = pbase + c;
            uint2 pv = make_uint2(0u, 0u);
            if ((unsigned)p < (unsigned)NP)
                pv = *(const uint2*)(Pg + (size_t)p * 64 + d4);
            int step = d4 >> 4, k16 = d4 & 15;
            unsigned a0 = step * 1024 + (c >> 3) * 64 + ((c & 7) * 4 + ((k16 & 7) >> 1)) * 2 + (k16 >> 3);
            sP[a0]     = pv.x;
            sP[a0 + 2] = pv.y;
        }
        __syncthreads();

        // content MMA (f16): 4 ksteps x 4 n8-tiles
        float C[4][4];
#pragma unroll
        for (int nt = 0; nt < 4; nt++)
#pragma unroll
            for (int r = 0; r < 4; r++) C[nt][r] = 0.f;
#pragma unroll
        for (int s = 0; s < 4; s++) {
#pragma unroll
            for (int nt = 0; nt < 4; nt++) {
                uint2 bv = *(const uint2*)&sKG[s * 520 + (ch * 4 + nt) * 64 + lam * 2];
                mma_f16(C[nt], qcf[s], bv);
            }
        }
        // G MMA (f16): band-pruned, 5 tiles per col-half
        float G[5][4];
#pragma unroll
        for (int nt = 0; nt < 5; nt++)
#pragma unroll
            for (int r = 0; r < 4; r++) G[nt][r] = 0.f;
#pragma unroll
        for (int s = 0; s < 4; s++) {
#pragma unroll
            for (int nt = 0; nt < 5; nt++) {
                int tg = gt0 + ch * 5 + nt;
                uint2 bv = *(const uint2*)&sP[s * 1024 + tg * 64 + lam * 2];
                mma_f16(G[nt], qpf[s], bv);
            }
        }
        __syncthreads();   // content reads of sKG done before G overwrite
#pragma unroll
        for (int nt = 0; nt < 5; nt++) {
            int c0 = (gt0 + ch * 5 + nt) * 8 + la2;
            *(__half2*)&sG[gr0 * 130 + c0]       = __floats2half2_rn(G[nt][0], G[nt][1]);
            *(__half2*)&sG[(gr0 + 8) * 130 + c0] = __floats2half2_rn(G[nt][2], G[nt][3]);
        }
        __syncthreads();   // G visible
#pragma unroll
        for (int nt = 0; nt < 4; nt++) {
            int jjb = ch * 32 + nt * 8 + la2;
            float s0 = C[nt][0] + __half2float(sG[gr0 * 130 + (jjb - gr0 + 63)]);
            float s1 = C[nt][1] + __half2float(sG[gr0 * 130 + (jjb + 1 - gr0 + 63)]);
            float s2 = C[nt][2] + __half2float(sG[(gr0 + 8) * 130 + (jjb - gr0 - 8 + 63)]);
            float s3 = C[nt][3] + __half2float(sG[(gr0 + 8) * 130 + (jjb + 1 - gr0 - 8 + 63)]);
            if (j0 + jjb < NL) {
                *(__half2*)&sS[gr0 * 520 + j0 + jjb]       = __floats2half2_rn(s0, s1);
                *(__half2*)&sS[(gr0 + 8) * 520 + j0 + jjb] = __floats2half2_rn(s2, s3);
            }
        }
    }
    __syncthreads();

    // prefetch V tile for jt=0 — latency hides under softmax.
    // thread covers keys {2*vkey + 32u, +1}, hd4..hd4+3.
    uint2 va[2], vb[2];
#define VGLOAD(J0) {                                                         \
        _Pragma("unroll")                                                    \
        for (int u = 0; u < 2; u++) {                                        \
            int k0 = (J0) + 2 * vkey + 32 * u;                               \
            va[u] = (k0 < NL)     ? *(const uint2*)(Vg + (size_t)k0 * 64 + vhd4)       : make_uint2(0u, 0u); \
            vb[u] = (k0 + 1 < NL) ? *(const uint2*)(Vg + (size_t)(k0 + 1) * 64 + vhd4) : make_uint2(0u, 0u); \
        } }
    VGLOAD(0);

    // ===================== softmax (warp per row, half2) =====================
    for (int li = w * 8; li < w * 8 + 8; li++) {
        int i = i0 + li;
        if (i >= NL) { if (lam == 0) sSum[li] = 1.f; continue; }
        const unsigned char* mrow = mask + ((size_t)b * NL + i) * NL;
        __half2* srow2 = (__half2*)&sS[li * 520];
        float mx = -3.4028235e38f;
        for (int j2 = lam; j2 < 256; j2 += 32) {
            float2 v = __half22float2(srow2[j2]);
            v.x = mrow[2 * j2]     ? -3.4028235e38f : v.x * 0.125f;
            v.y = mrow[2 * j2 + 1] ? -3.4028235e38f : v.y * 0.125f;
            mx = fmaxf(mx, fmaxf(v.x, v.y));
        }
        if (lam == 0) {
            float v = __half2float(sS[li * 520 + 512]) * 0.125f;
            if (mrow[512]) v = -3.4028235e38f;
            mx = fmaxf(mx, v);
        }
#pragma unroll
        for (int o = 16; o > 0; o >>= 1) mx = fmaxf(mx, __shfl_xor_sync(0xffffffffu, mx, o));
        float s = 0.f;
        for (int j2 = lam; j2 < 256; j2 += 32) {
            float2 v = __half22float2(srow2[j2]);
            v.x = mrow[2 * j2]     ? -3.4028235e38f : v.x * 0.125f;
            v.y = mrow[2 * j2 + 1] ? -3.4028235e38f : v.y * 0.125f;
            float e0 = __expf(v.x - mx), e1 = __expf(v.y - mx);
            srow2[j2] = __floats2half2_rn(e0, e1);
            s += e0 + e1;
        }
        if (lam == 0) {
            float v = __half2float(sS[li * 520 + 512]) * 0.125f;
            if (mrow[512]) v = -3.4028235e38f;
            float e = __expf(v - mx);
            sS[li * 520 + 512] = __float2half_rn(e);
            s += e;
        }
#pragma unroll
        for (int o = 16; o > 0; o >>= 1) s += __shfl_xor_sync(0xffffffffu, s, o);
        if (lam == 0) sSum[li] = s;
    }
    __syncthreads();

    // ===================== AV phase (f16, V prefetched) =====================
    float O[4][4];
#pragma unroll
    for (int nt = 0; nt < 4; nt++)
#pragma unroll
        for (int r = 0; r < 4; r++) O[nt][r] = 0.f;

    for (int jt = 0; jt < 9; jt++) {
        int j0 = jt * 64;
        // store prefetched V as f16 B-frags: k = key, n = hd
#pragma unroll
        for (int u = 0; u < 2; u++) {
            int key0 = 2 * vkey + 32 * u;        // even local key
            __half2 a01 = *(__half2*)&va[u].x;
            __half2 a23 = *(__half2*)&va[u].y;
            __half2 b01 = *(__half2*)&vb[u].x;
            __half2 b23 = *(__half2*)&vb[u].y;
            unsigned o0 = pkhh(a01.x, b01.x);
            unsigned o1 = pkhh(a01.y, b01.y);
            unsigned o2 = pkhh(a23.x, b23.x);
            unsigned o3 = pkhh(a23.y, b23.y);
            int step = key0 >> 4, kk = key0 & 15;
            unsigned koff = step * 520 + ((kk & 7) >> 1) * 2 + (kk >> 3);
#pragma unroll
            for (int e = 0; e < 4; e++) {
                int n = vhd4 + e;
                unsigned addr = koff + (n >> 3) * 64 + (n & 7) * 8;
                sKG[addr] = (e == 0) ? o0 : (e == 1) ? o1 : (e == 2) ? o2 : o3;
            }
        }
        __syncthreads();
        if (jt < 8) VGLOAD(j0 + 64);
#pragma unroll
        for (int ks = 0; ks < 4; ks++) {
            int kc0 = j0 + ks * 16 + la2;
            unsigned a0 = *(const unsigned*)&sS[gr0 * 520 + kc0];
            unsigned a1 = *(const unsigned*)&sS[(gr0 + 8) * 520 + kc0];
            unsigned a2 = *(const unsigned*)&sS[gr0 * 520 + kc0 + 8];
            unsigned a3 = *(const unsigned*)&sS[(gr0 + 8) * 520 + kc0 + 8];
            uint4 av = make_uint4(a0, a1, a2, a3);
#pragma unroll
            for (int nt = 0; nt < 4; nt++) {
                uint2 bv = *(const uint2*)&sKG[ks * 520 + (ch * 4 + nt) * 64 + lam * 2];
                mma_f16(O[nt], av, bv);
            }
        }
        __syncthreads();   // MMA reads of sKG done before next V store
    }
#undef VGLOAD

    float l0 = 1.f / sSum[gr0];
    float l1 = 1.f / sSum[gr0 + 8];
#pragma unroll
    for (int nt = 0; nt < 4; nt++) {
        int hd = ch * 32 + nt * 8 + la2;
        if (r0g < NL) {
            float2 st = make_float2(O[nt][0] * l0, O[nt][1] * l0);
            *(float2*)&ctx[((size_t)b * NL + r0g) * ND + h * 64 + hd] = st;
        }
        if (r1g < NL) {
            float2 st = make_float2(O[nt][2] * l1, O[nt][3] * l1);
            *(float2*)&ctx[((size_t)b * NL + r1g) * ND + h * 64 + hd] = st;
        }
    }
}

// ---------------------------------------------------------------------------
extern "C" void kernel_launch(void* const* d_in, const int* in_sizes, int n_in,
                              void* d_out, int out_size)
{
    const float* x     = (const float*)d_in[0];
    const float* pe    = (const float*)d_in[1];
    const unsigned char* mask = (const unsigned char*)d_in[2];
    const float* qkv_w = (const float*)d_in[3];
    const float* qkv_b = (const float*)d_in[4];
    const float* pos_w = (const float*)d_in[5];
    const float* pos_b = (const float*)d_in[6];
    const float* out_w = (const float*)d_in[7];
    const float* out_b = (const float*)d_in[8];
    const float* cbias = (const float*)d_in[9];
    const float* pbias = (const float*)d_in[10];
    float* out = (float*)d_out;

    float* ctxp = nullptr;
    cudaGetSymbolAddress((void**)&ctxp, g_CTX);

    const int M1 = NB * NL;                        // 8208
    const int GEMM_SMEM = 2 * (4240 + 4104) * 4;   // 66,752 B
    const int ATTN_SMEM = 99968;
    cudaFuncSetAttribute(gemm_tf32<0>, cudaFuncAttributeMaxDynamicSharedMemorySize, GEMM_SMEM);
    cudaFuncSetAttribute(gemm_tf32<1>, cudaFuncAttributeMaxDynamicSharedMemorySize, GEMM_SMEM);
    cudaFuncSetAttribute(gemm_tf32<2>, cudaFuncAttributeMaxDynamicSharedMemorySize, GEMM_SMEM);
    cudaFuncSetAttribute(attn_mma, cudaFuncAttributeMaxDynamicSharedMemorySize, ATTN_SMEM);

    dim3 blk(256);
    gemm_tf32<0><<<dim3(3072 / 128, (M1 + 127) / 128), blk, GEMM_SMEM>>>(
        x, qkv_w, M1, 3072, qkv_b, cbias, pbias, nullptr);
    gemm_tf32<1><<<dim3(16384 / 128, 1024 / 128), blk, GEMM_SMEM>>>(
        pos_w, pe, 1024, 16384, pos_b, nullptr, nullptr, nullptr);
    attn_mma<<<dim3(9, NH, NB), blk, ATTN_SMEM>>>(mask, ctxp);
    gemm_tf32<2><<<dim3(1024 / 128, (M1 + 127) / 128), blk, GEMM_SMEM>>>(
        ctxp, out_w, M1, 1024, out_b, nullptr, nullptr, out);
}

// round 10
// speedup vs baseline: 1.7423x; 1.2800x over previous
#include <cuda_runtime.h>
#include <cuda_fp16.h>
#include <math.h>

#define NB 16
#define NH 16
#define NHD 64
#define ND 1024
#define NL 513
#define NP 1024

// Scratch (allocation-free rule: __device__ globals). fp16 intermediates.
__device__ __half g_QCh[NB*NH*NL*NHD];   // q + content_bias, [b,h,l,hd]
__device__ __half g_QPh[NB*NH*NL*NHD];   // q + position_bias
__device__ __half g_Kh [NB*NH*NL*NHD];   // k
__device__ __half g_Vh [NB*NH*NL*NHD];   // v
__device__ __half g_PTh[NB*NH*NP*NHD];   // pos projected, [b,h,p,hd]
__device__ float  g_CTX[NB*NL*ND];       // attention output (fp32)

__device__ __forceinline__ void mma_f16(float* d, const uint4& a, const uint2& b) {
    asm volatile(
        "mma.sync.aligned.m16n8k16.row.col.f32.f16.f16.f32 "
        "{%0,%1,%2,%3}, {%4,%5,%6,%7}, {%8,%9}, {%0,%1,%2,%3};"
        : "+f"(d[0]), "+f"(d[1]), "+f"(d[2]), "+f"(d[3])
        : "r"(a.x), "r"(a.y), "r"(a.z), "r"(a.w), "r"(b.x), "r"(b.y));
}

__device__ __forceinline__ unsigned ldh2(const __half* p) {
    return *(const unsigned*)p;
}
__device__ __forceinline__ unsigned pkh2f(float x, float y) {
    __half2 h = __floats2half2_rn(x, y);
    return *(unsigned*)&h;
}
__device__ __forceinline__ unsigned pkhh(__half x, __half y) {
    __half2 h = __halves2half2(x, y);
    return *(unsigned*)&h;
}

// ---------------------------------------------------------------------------
// f16 tensor-core GEMM (m16n8k16), double-buffered BK=32, ONE barrier/chunk:
//   GLOAD(c+1) -> regs; MMA(buf cur); SSTORE(buf 1-cur); bar.
// fp32 gmem sources converted to half2 pairs during staging (same mantissa
// as tf32 -> no accuracy change). 256 thr / 8 warps (2M x 4N of 64x32 tiles).
// Dynamic smem 33,376 B.
// ---------------------------------------------------------------------------
template<int EPI>
__global__ void __launch_bounds__(256, 2)
gemm_f16(const float* __restrict__ A, const float* __restrict__ Bw,
         int M, int N,
         const float* __restrict__ bias,
         const float* __restrict__ cbias, const float* __restrict__ pbias,
         float* __restrict__ out)
{
    const int K = 1024;
    extern __shared__ unsigned gsm[];
    unsigned* sA = gsm;            // 2 x 2120 (two k16-steps of A frags)
    unsigned* sB = gsm + 2 * 2120; // 2 x 2052

    int t    = threadIdx.x;
    int lane = t & 31, w = t >> 5;
    int warpM = w & 1, warpN = w >> 1;
    int m0 = blockIdx.y * 128, n0 = blockIdx.x * 128;

    int lrow = t >> 3;        // 0..31
    int lkq  = t & 7;
    int kk0  = lkq * 4;       // k offset within 32-wide chunk
    int sstep = kk0 >> 4;     // which k16-step
    int c16  = kk0 & 15;      // 0,4,8,12

    // fragment staging addresses (pair2 at +4 for A, +2 for B)
    unsigned baA[4], baB[4];
#pragma unroll
    for (int u = 0; u < 4; u++) {
        int ml = lrow + u * 32;
        int mt = ml >> 4, mr = ml & 15;
        baA[u] = sstep * 1060 + mt * 132
               + ((mr & 7) * 4 + ((c16 & 7) >> 1)) * 4
               + (c16 >> 3) * 2 + (mr >> 3);
        baB[u] = sstep * 1026 + (ml >> 3) * 64
               + ((ml & 7) * 4 + ((c16 & 7) >> 1)) * 2
               + (c16 >> 3);
    }

    float acc[4][4][4];
#pragma unroll
    for (int i = 0; i < 4; i++)
#pragma unroll
        for (int j = 0; j < 4; j++)
#pragma unroll
            for (int r = 0; r < 4; r++) acc[i][j][r] = 0.f;

    float4 ra[4], rb[4];
    const float4 z4 = make_float4(0.f, 0.f, 0.f, 0.f);

#define GLOAD(KT) {                                                          \
        _Pragma("unroll")                                                    \
        for (int u = 0; u < 4; u++) {                                        \
            int gm = m0 + lrow + u * 32;                                     \
            ra[u] = (gm < M) ? *(const float4*)(A + (size_t)gm * K + (KT) + kk0) : z4; \
            rb[u] = *(const float4*)(Bw + (size_t)(n0 + lrow + u * 32) * K + (KT) + kk0); \
        } }

#define SSTORE(BI) {                                                         \
        _Pragma("unroll")                                                    \
        for (int u = 0; u < 4; u++) {                                        \
            unsigned ba = (BI) * 2120 + baA[u];                              \
            sA[ba + 0] = pkh2f(ra[u].x, ra[u].y);                            \
            sA[ba + 4] = pkh2f(ra[u].z, ra[u].w);                            \
            unsigned bb = (BI) * 2052 + baB[u];                              \
            sB[bb + 0] = pkh2f(rb[u].x, rb[u].y);                            \
            sB[bb + 2] = pkh2f(rb[u].z, rb[u].w);                            \
        } }

    GLOAD(0);
    SSTORE(0);
    __syncthreads();

    for (int c = 0; c < 32; c++) {
        int cur = c & 1;
        if (c < 31) GLOAD((c + 1) * 32);
#pragma unroll
        for (int s = 0; s < 2; s++) {
            uint4 av[4];
            uint2 bv[4];
#pragma unroll
            for (int i = 0; i < 4; i++)
                av[i] = *(const uint4*)&sA[cur * 2120 + s * 1060 + (warpM * 4 + i) * 132 + lane * 4];
#pragma unroll
            for (int j = 0; j < 4; j++)
                bv[j] = *(const uint2*)&sB[cur * 2052 + s * 1026 + (warpN * 4 + j) * 64 + lane * 2];
#pragma unroll
            for (int i = 0; i < 4; i++)
#pragma unroll
                for (int j = 0; j < 4; j++)
                    mma_f16(acc[i][j], av[i], bv[j]);
        }
        if (c < 31) SSTORE(1 - cur);
        __syncthreads();
    }
#undef GLOAD
#undef SSTORE

    int mb = m0 + warpM * 64 + (lane >> 2);
    int nb = n0 + warpN * 32 + (lane & 3) * 2;
#pragma unroll
    for (int i = 0; i < 4; i++) {
#pragma unroll
        for (int rr = 0; rr < 2; rr++) {
            int m = mb + i * 16 + rr * 8;
            if (m >= M) continue;
            if (EPI == 0) {
                int b_ = m / NL, l = m - b_ * NL;
#pragma unroll
                for (int j = 0; j < 4; j++) {
                    int n = nb + j * 8;            // even; pair (n, n+1) same part/head
                    float v0 = acc[i][j][rr * 2 + 0] + bias[n];
                    float v1 = acc[i][j][rr * 2 + 1] + bias[n + 1];
                    int part = n >> 10, c1 = n & 1023;
                    int hh = c1 >> 6, hd = c1 & 63;
                    size_t o = ((((size_t)b_ * NH + hh) * NL + l) << 6) + hd;
                    if (part == 0) {
                        *(unsigned*)&g_QCh[o] = pkh2f(v0 + cbias[c1], v1 + cbias[c1 + 1]);
                        *(unsigned*)&g_QPh[o] = pkh2f(v0 + pbias[c1], v1 + pbias[c1 + 1]);
                    } else if (part == 1) {
                        *(unsigned*)&g_Kh[o] = pkh2f(v0, v1);
                    } else {
                        *(unsigned*)&g_Vh[o] = pkh2f(v0, v1);
                    }
                }
            } else if (EPI == 1) {
                float bm = bias[m];
#pragma unroll
                for (int j = 0; j < 4; j++) {
                    int n = nb + j * 8;
                    float v0 = acc[i][j][rr * 2 + 0] + bm;
                    float v1 = acc[i][j][rr * 2 + 1] + bm;
                    int bh = n >> 6, hd = n & 63;
                    *(unsigned*)&g_PTh[((((size_t)bh) << 10) + m) * 64 + hd] = pkh2f(v0, v1);
                }
            } else {
#pragma unroll
                for (int j = 0; j < 4; j++) {
                    int n = nb + j * 8;
                    float2 st;
                    st.x = acc[i][j][rr * 2 + 0] + bias[n];
                    st.y = acc[i][j][rr * 2 + 1] + bias[n + 1];
                    *(float2*)(out + (size_t)m * ND + n) = st;
                }
            }
        }
    }
}

// ---------------------------------------------------------------------------
// Tensor-core fused attention, all-f16 MMA inputs (unchanged from R9).
// CTA = (i-tile of 64 q, one b,h), 256 thr / 8 warps: rg=w&3 (16 rows),
// ch=w>>2 (col half). Q frags register-resident. smem 99,968B -> 2 CTAs/SM.
// ---------------------------------------------------------------------------
__global__ void __launch_bounds__(256, 2)
attn_mma(const unsigned char* __restrict__ mask, float* __restrict__ ctx)
{
    extern __shared__ char smraw[];
    __half*   sS  = (__half*)smraw;                   // [64][520] + 64 pad (66,688B)
    unsigned* sKG = (unsigned*)(smraw + 66688);       // K/V f16 frags | G (16,640B)
    unsigned* sP  = (unsigned*)(smraw + 83328);       // P band f16 frags (16,384B)
    float*    sSum= (float*)(smraw + 99712);          // [64]
    __half*   sG  = (__half*)sKG;                     // G view: [64][130] halves

    int t = threadIdx.x, lam = t & 31, w = t >> 5;
    int rg = w & 3, ch = w >> 2;
    int it = blockIdx.x, h = blockIdx.y, b = blockIdx.z;
    int i0 = it * 64;
    size_t bh = (size_t)b * NH + h;
    const __half* QCg = g_QCh + bh * NL * NHD;
    const __half* QPg = g_QPh + bh * NL * NHD;
    const __half* Kg  = g_Kh  + bh * NL * NHD;
    const __half* Vg  = g_Vh  + bh * NL * NHD;
    const __half* Pg  = g_PTh + bh * NP * NHD;

    // zero sS (incl. pads)
    for (int idx = t; idx < 16672; idx += 256) ((unsigned*)sS)[idx] = 0u;

    int gr0 = rg * 16 + (lam >> 2);
    int r0g = i0 + gr0, r1g = r0g + 8;
    int gt0 = 6 - 2 * rg;      // first G n8-tile needed by this row group

    int vkey = t >> 4;         // staging key base
    int vhd4 = (t & 15) * 4;   // staging hd base
    int la2  = (lam & 3) * 2;

    // QC / QP A-frags (f16, m16n8k16): 4 ksteps, register-resident
    uint4 qcf[4], qpf[4];
#pragma unroll
    for (int s = 0; s < 4; s++) {
        int c0 = s * 16 + la2;
        unsigned c00 = (r0g < NL) ? ldh2(QCg + r0g * 64 + c0)     : 0u;
        unsigned c10 = (r1g < NL) ? ldh2(QCg + r1g * 64 + c0)     : 0u;
        unsigned c01 = (r0g < NL) ? ldh2(QCg + r0g * 64 + c0 + 8) : 0u;
        unsigned c11 = (r1g < NL) ? ldh2(QCg + r1g * 64 + c0 + 8) : 0u;
        qcf[s] = make_uint4(c00, c10, c01, c11);
        unsigned p00 = (r0g < NL) ? ldh2(QPg + r0g * 64 + c0)     : 0u;
        unsigned p10 = (r1g < NL) ? ldh2(QPg + r1g * 64 + c0)     : 0u;
        unsigned p01 = (r0g < NL) ? ldh2(QPg + r0g * 64 + c0 + 8) : 0u;
        unsigned p11 = (r1g < NL) ? ldh2(QPg + r1g * 64 + c0 + 8) : 0u;
        qpf[s] = make_uint4(p00, p10, p01, p11);
    }

    // ===================== score phase =====================
    for (int jt = 0; jt < 9; jt++) {
        int j0 = jt * 64;
        __syncthreads();
        // stage K_j as f16 B-frags (k = hd, n = key); 4 steps x 520 uints
        {
            int step = vhd4 >> 4, k16 = vhd4 & 15;
            unsigned boff = step * 520 + ((k16 & 7) >> 1) * 2 + (k16 >> 3);
#pragma unroll
            for (int u = 0; u < 4; u++) {
                int key = vkey + u * 16;
                int gk = j0 + key;
                uint2 kv = make_uint2(0u, 0u);
                if (gk < NL) kv = *(const uint2*)(Kg + (size_t)gk * 64 + vhd4);
                unsigned base = boff + (key >> 3) * 64 + (key & 7) * 8;
                sKG[base]     = kv.x;
                sKG[base + 2] = kv.y;
            }
        }
        // stage P band (128 rows x 64 hd) as f16 B-frags (k = hd, n = c)
        int pbase = j0 - i0 + 449;
#pragma unroll
        for (int u = 0; u < 8; u++) {
            int idx = u * 256 + t;
            int c = idx >> 4, d4 = (idx & 15) * 4;
            int p = pbase + c;
            uint2 pv = make_uint2(0u, 0u);
            if ((unsigned)p < (unsigned)NP)
                pv = *(const uint2*)(Pg + (size_t)p * 64 + d4);
            int step = d4 >> 4, k16 = d4 & 15;
            unsigned a0 = step * 1024 + (c >> 3) * 64 + ((c & 7) * 4 + ((k16 & 7) >> 1)) * 2 + (k16 >> 3);
            sP[a0]     = pv.x;
            sP[a0 + 2] = pv.y;
        }
        __syncthreads();

        // content MMA (f16): 4 ksteps x 4 n8-tiles
        float C[4][4];
#pragma unroll
        for (int nt = 0; nt < 4; nt++)
#pragma unroll
            for (int r = 0; r < 4; r++) C[nt][r] = 0.f;
#pragma unroll
        for (int s = 0; s < 4; s++) {
#pragma unroll
            for (int nt = 0; nt < 4; nt++) {
                uint2 bv = *(const uint2*)&sKG[s * 520 + (ch * 4 + nt) * 64 + lam * 2];
                mma_f16(C[nt], qcf[s], bv);
            }
        }
        // G MMA (f16): band-pruned, 5 tiles per col-half
        float G[5][4];
#pragma unroll
        for (int nt = 0; nt < 5; nt++)
#pragma unroll
            for (int r = 0; r < 4; r++) G[nt][r] = 0.f;
#pragma unroll
        for (int s = 0; s < 4; s++) {
#pragma unroll
            for (int nt = 0; nt < 5; nt++) {
                int tg = gt0 + ch * 5 + nt;
                uint2 bv = *(const uint2*)&sP[s * 1024 + tg * 64 + lam * 2];
                mma_f16(G[nt], qpf[s], bv);
            }
        }
        __syncthreads();   // content reads of sKG done before G overwrite
#pragma unroll
        for (int nt = 0; nt < 5; nt++) {
            int c0 = (gt0 + ch * 5 + nt) * 8 + la2;
            *(__half2*)&sG[gr0 * 130 + c0]       = __floats2half2_rn(G[nt][0], G[nt][1]);
            *(__half2*)&sG[(gr0 + 8) * 130 + c0] = __floats2half2_rn(G[nt][2], G[nt][3]);
        }
        __syncthreads();   // G visible
#pragma unroll
        for (int nt = 0; nt < 4; nt++) {
            int jjb = ch * 32 + nt * 8 + la2;
            float s0 = C[nt][0] + __half2float(sG[gr0 * 130 + (jjb - gr0 + 63)]);
            float s1 = C[nt][1] + __half2float(sG[gr0 * 130 + (jjb + 1 - gr0 + 63)]);
            float s2 = C[nt][2] + __half2float(sG[(gr0 + 8) * 130 + (jjb - gr0 - 8 + 63)]);
            float s3 = C[nt][3] + __half2float(sG[(gr0 + 8) * 130 + (jjb + 1 - gr0 - 8 + 63)]);
            if (j0 + jjb < NL) {
                *(__half2*)&sS[gr0 * 520 + j0 + jjb]       = __floats2half2_rn(s0, s1);
                *(__half2*)&sS[(gr0 + 8) * 520 + j0 + jjb] = __floats2half2_rn(s2, s3);
            }
        }
    }
    __syncthreads();

    // prefetch V tile for jt=0 — latency hides under softmax.
    uint2 va[2], vb[2];
#define VGLOAD(J0) {                                                         \
        _Pragma("unroll")                                                    \
        for (int u = 0; u < 2; u++) {                                        \
            int k0 = (J0) + 2 * vkey + 32 * u;                               \
            va[u] = (k0 < NL)     ? *(const uint2*)(Vg + (size_t)k0 * 64 + vhd4)       : make_uint2(0u, 0u); \
            vb[u] = (k0 + 1 < NL) ? *(const uint2*)(Vg + (size_t)(k0 + 1) * 64 + vhd4) : make_uint2(0u, 0u); \
        } }
    VGLOAD(0);

    // ===================== softmax (warp per row, half2) =====================
    for (int li = w * 8; li < w * 8 + 8; li++) {
        int i = i0 + li;
        if (i >= NL) { if (lam == 0) sSum[li] = 1.f; continue; }
        const unsigned char* mrow = mask + ((size_t)b * NL + i) * NL;
        __half2* srow2 = (__half2*)&sS[li * 520];
        float mx = -3.4028235e38f;
        for (int j2 = lam; j2 < 256; j2 += 32) {
            float2 v = __half22float2(srow2[j2]);
            v.x = mrow[2 * j2]     ? -3.4028235e38f : v.x * 0.125f;
            v.y = mrow[2 * j2 + 1] ? -3.4028235e38f : v.y * 0.125f;
            mx = fmaxf(mx, fmaxf(v.x, v.y));
        }
        if (lam == 0) {
            float v = __half2float(sS[li * 520 + 512]) * 0.125f;
            if (mrow[512]) v = -3.4028235e38f;
            mx = fmaxf(mx, v);
        }
#pragma unroll
        for (int o = 16; o > 0; o >>= 1) mx = fmaxf(mx, __shfl_xor_sync(0xffffffffu, mx, o));
        float s = 0.f;
        for (int j2 = lam; j2 < 256; j2 += 32) {
            float2 v = __half22float2(srow2[j2]);
            v.x = mrow[2 * j2]     ? -3.4028235e38f : v.x * 0.125f;
            v.y = mrow[2 * j2 + 1] ? -3.4028235e38f : v.y * 0.125f;
            float e0 = __expf(v.x - mx), e1 = __expf(v.y - mx);
            srow2[j2] = __floats2half2_rn(e0, e1);
            s += e0 + e1;
        }
        if (lam == 0) {
            float v = __half2float(sS[li * 520 + 512]) * 0.125f;
            if (mrow[512]) v = -3.4028235e38f;
            float e = __expf(v - mx);
            sS[li * 520 + 512] = __float2half_rn(e);
            s += e;
        }
#pragma unroll
        for (int o = 16; o > 0; o >>= 1) s += __shfl_xor_sync(0xffffffffu, s, o);
        if (lam == 0) sSum[li] = s;
    }
    __syncthreads();

    // ===================== AV phase (f16, V prefetched) =====================
    float O[4][4];
#pragma unroll
    for (int nt = 0; nt < 4; nt++)
#pragma unroll
        for (int r = 0; r < 4; r++) O[nt][r] = 0.f;

    for (int jt = 0; jt < 9; jt++) {
        int j0 = jt * 64;
        // store prefetched V as f16 B-frags: k = key, n = hd
#pragma unroll
        for (int u = 0; u < 2; u++) {
            int key0 = 2 * vkey + 32 * u;        // even local key
            __half2 a01 = *(__half2*)&va[u].x;
            __half2 a23 = *(__half2*)&va[u].y;
            __half2 b01 = *(__half2*)&vb[u].x;
            __half2 b23 = *(__half2*)&vb[u].y;
            unsigned o0 = pkhh(a01.x, b01.x);
            unsigned o1 = pkhh(a01.y, b01.y);
            unsigned o2 = pkhh(a23.x, b23.x);
            unsigned o3 = pkhh(a23.y, b23.y);
            int step = key0 >> 4, kk = key0 & 15;
            unsigned koff = step * 520 + ((kk & 7) >> 1) * 2 + (kk >> 3);
#pragma unroll
            for (int e = 0; e < 4; e++) {
                int n = vhd4 + e;
                unsigned addr = koff + (n >> 3) * 64 + (n & 7) * 8;
                sKG[addr] = (e == 0) ? o0 : (e == 1) ? o1 : (e == 2) ? o2 : o3;
            }
        }
        __syncthreads();
        if (jt < 8) VGLOAD(j0 + 64);
#pragma unroll
        for (int ks = 0; ks < 4; ks++) {
            int kc0 = j0 + ks * 16 + la2;
            unsigned a0 = *(const unsigned*)&sS[gr0 * 520 + kc0];
            unsigned a1 = *(const unsigned*)&sS[(gr0 + 8) * 520 + kc0];
            unsigned a2 = *(const unsigned*)&sS[gr0 * 520 + kc0 + 8];
            unsigned a3 = *(const unsigned*)&sS[(gr0 + 8) * 520 + kc0 + 8];
            uint4 av = make_uint4(a0, a1, a2, a3);
#pragma unroll
            for (int nt = 0; nt < 4; nt++) {
                uint2 bv = *(const uint2*)&sKG[ks * 520 + (ch * 4 + nt) * 64 + lam * 2];
                mma_f16(O[nt], av, bv);
            }
        }
        __syncthreads();   // MMA reads of sKG done before next V store
    }
#undef VGLOAD

    float l0 = 1.f / sSum[gr0];
    float l1 = 1.f / sSum[gr0 + 8];
#pragma unroll
    for (int nt = 0; nt < 4; nt++) {
        int hd = ch * 32 + nt * 8 + la2;
        if (r0g < NL) {
            float2 st = make_float2(O[nt][0] * l0, O[nt][1] * l0);
            *(float2*)&ctx[((size_t)b * NL + r0g) * ND + h * 64 + hd] = st;
        }
        if (r1g < NL) {
            float2 st = make_float2(O[nt][2] * l1, O[nt][3] * l1);
            *(float2*)&ctx[((size_t)b * NL + r1g) * ND + h * 64 + hd] = st;
        }
    }
}

// ---------------------------------------------------------------------------
extern "C" void kernel_launch(void* const* d_in, const int* in_sizes, int n_in,
                              void* d_out, int out_size)
{
    const float* x     = (const float*)d_in[0];
    const float* pe    = (const float*)d_in[1];
    const unsigned char* mask = (const unsigned char*)d_in[2];
    const float* qkv_w = (const float*)d_in[3];
    const float* qkv_b = (const float*)d_in[4];
    const float* pos_w = (const float*)d_in[5];
    const float* pos_b = (const float*)d_in[6];
    const float* out_w = (const float*)d_in[7];
    const float* out_b = (const float*)d_in[8];
    const float* cbias = (const float*)d_in[9];
    const float* pbias = (const float*)d_in[10];
    float* out = (float*)d_out;

    float* ctxp = nullptr;
    cudaGetSymbolAddress((void**)&ctxp, g_CTX);

    const int M1 = NB * NL;                        // 8208
    const int GEMM_SMEM = 2 * (2120 + 2052) * 4;   // 33,376 B
    const int ATTN_SMEM = 99968;
    cudaFuncSetAttribute(gemm_f16<0>, cudaFuncAttributeMaxDynamicSharedMemorySize, GEMM_SMEM);
    cudaFuncSetAttribute(gemm_f16<1>, cudaFuncAttributeMaxDynamicSharedMemorySize, GEMM_SMEM);
    cudaFuncSetAttribute(gemm_f16<2>, cudaFuncAttributeMaxDynamicSharedMemorySize, GEMM_SMEM);
    cudaFuncSetAttribute(attn_mma, cudaFuncAttributeMaxDynamicSharedMemorySize, ATTN_SMEM);

    dim3 blk(256);
    gemm_f16<0><<<dim3(3072 / 128, (M1 + 127) / 128), blk, GEMM_SMEM>>>(
        x, qkv_w, M1, 3072, qkv_b, cbias, pbias, nullptr);
    gemm_f16<1><<<dim3(16384 / 128, 1024 / 128), blk, GEMM_SMEM>>>(
        pos_w, pe, 1024, 16384, pos_b, nullptr, nullptr, nullptr);
    attn_mma<<<dim3(9, NH, NB), blk, ATTN_SMEM>>>(mask, ctxp);
    gemm_f16<2><<<dim3(1024 / 128, (M1 + 127) / 128), blk, GEMM_SMEM>>>(
        ctxp, out_w, M1, 1024, out_b, nullptr, nullptr, out);
}